// round 13
// baseline (speedup 1.0000x reference)
#include <cuda_runtime.h>
#include <cuda_bf16.h>
#include <cstdint>
#include <math.h>

#define S_LEN   2048
#define D_MODEL 1024
#define N_HEADS 16
#define IDX_D   256
#define MAXB    2
#define BS_MAX  (MAXB * S_LEN)

typedef __nv_bfloat16 bf16;

// ---------------- scratch (static device globals; no allocation) ----------------
__device__ float    g_qkv [(size_t)BS_MAX * 3 * D_MODEL];
__device__ float    g_iq  [(size_t)BS_MAX * IDX_D];
__device__ float    g_ik  [(size_t)BS_MAX * IDX_D];
__device__ unsigned g_mask[(size_t)BS_MAX * (S_LEN / 32)];

__device__ __align__(16) bf16 g_x3   [(size_t)BS_MAX * 3 * D_MODEL];
__device__ __align__(16) bf16 g_attn3[(size_t)BS_MAX * 3 * D_MODEL];
__device__ __align__(16) bf16 g_wqkv3[(size_t)(3 * D_MODEL) * 3 * D_MODEL];
__device__ __align__(16) bf16 g_wo3  [(size_t)D_MODEL * 3 * D_MODEL];

// flash operands: h/l split pairs
__device__ __align__(16) bf16 g_qh [(size_t)MAXB * N_HEADS * S_LEN * 64];
__device__ __align__(16) bf16 g_ql [(size_t)MAXB * N_HEADS * S_LEN * 64];
__device__ __align__(16) bf16 g_kh [(size_t)MAXB * N_HEADS * S_LEN * 64];
__device__ __align__(16) bf16 g_kl [(size_t)MAXB * N_HEADS * S_LEN * 64];
__device__ __align__(16) bf16 g_vth[(size_t)MAXB * N_HEADS * 64 * S_LEN];
__device__ __align__(16) bf16 g_vtl[(size_t)MAXB * N_HEADS * 64 * S_LEN];

// ---------------- bf16x3 split conversions --------------------------------------
__global__ void split_a(const float* __restrict__ s, bf16* __restrict__ d, int n)
{
    int i = blockIdx.x * blockDim.x + threadIdx.x;
    if (i >= n) return;
    float v = s[i];
    bf16 h = __float2bfloat16(v);
    bf16 l = __float2bfloat16(v - __bfloat162float(h));
    d[3 * i] = h; d[3 * i + 1] = l; d[3 * i + 2] = h;
}

__global__ void split_bT(const float* __restrict__ W, bf16* __restrict__ out,
                         int K, int N)
{
    __shared__ float t[32][33];
    int n0 = blockIdx.x * 32, k0 = blockIdx.y * 32;
    int tx = threadIdx.x, ty = threadIdx.y;   // block (32,8)
    for (int i = ty; i < 32; i += 8)
        t[i][tx] = W[(size_t)(k0 + i) * N + n0 + tx];
    __syncthreads();
    for (int r = ty; r < 32; r += 8) {
        float v = t[tx][r];
        bf16 h = __float2bfloat16(v);
        bf16 l = __float2bfloat16(v - __bfloat162float(h));
        size_t o = (size_t)(n0 + r) * (3 * K) + 3 * (size_t)(k0 + tx);
        out[o] = h; out[o + 1] = h; out[o + 2] = l;
    }
}

// ---------------- tensor-core NT GEMM, 3-stage pipeline, paired B-ldsm ----------
#define BMg 128
#define BNg 128
#define BKg 32
#define GEMM_SMEM (3 * (BMg + BNg) * 40 * 2)   // 61440 bytes

__device__ __forceinline__ void ldsm_x4(uint32_t* r, uint32_t a) {
    asm volatile("ldmatrix.sync.aligned.m8n8.x4.shared.b16 {%0,%1,%2,%3}, [%4];"
                 : "=r"(r[0]), "=r"(r[1]), "=r"(r[2]), "=r"(r[3]) : "r"(a));
}
__device__ __forceinline__ void mma16816(float* c, const uint32_t* a, const uint32_t* b) {
    asm volatile("mma.sync.aligned.m16n8k16.row.col.f32.bf16.bf16.f32 "
                 "{%0,%1,%2,%3},{%4,%5,%6,%7},{%8,%9},{%0,%1,%2,%3};"
                 : "+f"(c[0]), "+f"(c[1]), "+f"(c[2]), "+f"(c[3])
                 : "r"(a[0]), "r"(a[1]), "r"(a[2]), "r"(a[3]), "r"(b[0]), "r"(b[1]));
}
#define CP16(sa, ga) asm volatile("cp.async.cg.shared.global [%0], [%1], 16;\n" :: "r"(sa), "l"(ga))
#define CPCOMMIT()   asm volatile("cp.async.commit_group;\n" ::: "memory")
#define CPWAIT0()    asm volatile("cp.async.wait_group 0;\n" ::: "memory")
#define CPWAIT1()    asm volatile("cp.async.wait_group 1;\n" ::: "memory")

__global__ __launch_bounds__(256) void mma_gemm(
    const bf16* __restrict__ A, const bf16* __restrict__ B, float* __restrict__ C,
    int M, int N, int K)
{
    extern __shared__ __align__(16) bf16 gsm[];
    const int bx = blockIdx.x, by = blockIdx.y;

    const int tid  = threadIdx.x;
    const int warp = tid >> 5, lane = tid & 31;
    const int wm = warp & 1, wn = warp >> 1;

    const uint32_t BUFA  = BMg * 40 * 2;
    const uint32_t BUFAB = (BMg + BNg) * 40 * 2;
    const uint32_t sbase = (uint32_t)__cvta_generic_to_shared(gsm);
    const uint32_t sA = sbase;
    const uint32_t sB = sbase + BUFA;

    const int ldrow = tid >> 2;
    const int ldch  = (tid & 3) * 8;

    float acc[4][4][4];
#pragma unroll
    for (int i = 0; i < 4; i++)
#pragma unroll
        for (int j = 0; j < 4; j++)
#pragma unroll
            for (int t = 0; t < 4; t++) acc[i][j][t] = 0.f;

    const int KT = K / BKg;

#pragma unroll
    for (int pf = 0; pf < 2; pf++) {
        int k0 = pf * BKg;
#pragma unroll
        for (int h = 0; h < 2; h++) {
            int row = ldrow + h * 64;
            CP16(sA + pf * BUFAB + (uint32_t)(row * 40 + ldch) * 2,
                 A + (size_t)(by * BMg + row) * K + k0 + ldch);
            CP16(sB + pf * BUFAB + (uint32_t)(row * 40 + ldch) * 2,
                 B + (size_t)(bx * BNg + row) * K + k0 + ldch);
        }
        CPCOMMIT();
    }
    CPWAIT1();
    __syncthreads();

    // paired-B addressing (same scheme as flash: bb[0..1]=rows 0-7, bb[2..3]=rows 8-15)
    const int browo = (lane & 7) + ((lane >> 4) << 3);
    const int bkoff = (((lane >> 3) & 1) << 3);

    for (int kt = 0; kt < KT; kt++) {
        const uint32_t bo = (uint32_t)(kt % 3) * BUFAB;

#pragma unroll
        for (int ks = 0; ks < BKg; ks += 16) {
            uint32_t af[4][4], bfr[2][4];
            const int arow = wm * 64 + (lane & 15);
            const int acol = ks + ((lane >> 4) << 3);
#pragma unroll
            for (int mt = 0; mt < 4; mt++)
                ldsm_x4(af[mt], sA + bo +
                        (uint32_t)((arow + mt * 16) * 40 + acol) * 2);
#pragma unroll
            for (int nt2 = 0; nt2 < 2; nt2++)
                ldsm_x4(bfr[nt2], sB + bo +
                        (uint32_t)((wn * 32 + nt2 * 16 + browo) * 40 + ks + bkoff) * 2);
#pragma unroll
            for (int mt = 0; mt < 4; mt++)
#pragma unroll
                for (int nt = 0; nt < 4; nt++)
                    mma16816(acc[mt][nt], af[mt], bfr[nt >> 1] + (nt & 1) * 2);
        }

        __syncthreads();
        if (kt + 2 < KT) {
            const uint32_t po = (uint32_t)((kt + 2) % 3) * BUFAB;
            const int k0 = (kt + 2) * BKg;
#pragma unroll
            for (int h = 0; h < 2; h++) {
                int row = ldrow + h * 64;
                CP16(sA + po + (uint32_t)(row * 40 + ldch) * 2,
                     A + (size_t)(by * BMg + row) * K + k0 + ldch);
                CP16(sB + po + (uint32_t)(row * 40 + ldch) * 2,
                     B + (size_t)(bx * BNg + row) * K + k0 + ldch);
            }
            CPCOMMIT();
        }
        if (kt + 1 < KT) {
            if (kt + 2 < KT) CPWAIT1(); else CPWAIT0();
            __syncthreads();
        }
    }

#pragma unroll
    for (int mt = 0; mt < 4; mt++) {
#pragma unroll
        for (int nt = 0; nt < 4; nt++) {
            int row = by * BMg + wm * 64 + mt * 16 + (lane >> 2);
            int col = bx * BNg + wn * 32 + nt * 8 + (lane & 3) * 2;
            float2 v0 = make_float2(acc[mt][nt][0], acc[mt][nt][1]);
            float2 v1 = make_float2(acc[mt][nt][2], acc[mt][nt][3]);
            *(float2*)&C[(size_t)row * N + col]       = v0;
            *(float2*)&C[(size_t)(row + 8) * N + col] = v1;
        }
    }
}

// ---------------- fp32 SGEMM, dual-output (selection path, validated) -----------
__global__ __launch_bounds__(256) void sgemm_nn2(const float* __restrict__ A,
                                                 const float* __restrict__ B1,
                                                 float* __restrict__ C1,
                                                 const float* __restrict__ B2,
                                                 float* __restrict__ C2,
                                                 int M, int N, int K)
{
    const float* B = blockIdx.z ? B2 : B1;
    float*       C = blockIdx.z ? C2 : C1;

    __shared__ float As[2][8][128];
    __shared__ float Bs[2][8][128];

    const int tid = threadIdx.x;
    const int bx = blockIdx.x, by = blockIdx.y;
    const int tx = tid & 15, ty = tid >> 4;

    const int arow = tid >> 1, ak = (tid & 1) * 4;
    const int brow = tid >> 5, bcol = (tid & 31) * 4;

    const float* Ag = A + (size_t)(by * 128 + arow) * K + ak;
    const float* Bg = B + (size_t)brow * N + bx * 128 + bcol;

    float4 af = *(const float4*)Ag;
    float4 bf = *(const float4*)Bg;
    As[0][ak + 0][arow] = af.x;
    As[0][ak + 1][arow] = af.y;
    As[0][ak + 2][arow] = af.z;
    As[0][ak + 3][arow] = af.w;
    *(float4*)&Bs[0][brow][bcol] = bf;
    __syncthreads();

    float acc[8][8];
#pragma unroll
    for (int i = 0; i < 8; i++)
#pragma unroll
        for (int j = 0; j < 8; j++) acc[i][j] = 0.f;

    int buf = 0;
    for (int k0 = 8; k0 <= K; k0 += 8) {
        const bool next = (k0 < K);
        if (next) {
            af = *(const float4*)(Ag + k0);
            bf = *(const float4*)(Bg + (size_t)k0 * N);
        }
#pragma unroll
        for (int kk = 0; kk < 8; kk++) {
            float a[8], b[8];
            *(float4*)&a[0] = *(const float4*)&As[buf][kk][ty * 8];
            *(float4*)&a[4] = *(const float4*)&As[buf][kk][ty * 8 + 4];
            *(float4*)&b[0] = *(const float4*)&Bs[buf][kk][tx * 8];
            *(float4*)&b[4] = *(const float4*)&Bs[buf][kk][tx * 8 + 4];
#pragma unroll
            for (int i = 0; i < 8; i++)
#pragma unroll
                for (int j = 0; j < 8; j++)
                    acc[i][j] += a[i] * b[j];
        }
        if (next) {
            buf ^= 1;
            As[buf][ak + 0][arow] = af.x;
            As[buf][ak + 1][arow] = af.y;
            As[buf][ak + 2][arow] = af.z;
            As[buf][ak + 3][arow] = af.w;
            *(float4*)&Bs[buf][brow][bcol] = bf;
            __syncthreads();
        }
    }

#pragma unroll
    for (int i = 0; i < 8; i++) {
        float* Crow = C + (size_t)(by * 128 + ty * 8 + i) * N + bx * 128 + tx * 8;
        *(float4*)Crow       = make_float4(acc[i][0], acc[i][1], acc[i][2], acc[i][3]);
        *(float4*)(Crow + 4) = make_float4(acc[i][4], acc[i][5], acc[i][6], acc[i][7]);
    }
}

// ---------------- top-k: 8 rows/block, warp-parallel radix (validated) ----------
__global__ __launch_bounds__(256) void topk8_kernel(const float* __restrict__ iq,
                                                    const float* __restrict__ ik,
                                                    const int* __restrict__ topk_ptr,
                                                    unsigned* __restrict__ mask)
{
    extern __shared__ __align__(16) unsigned dsm[];
    float*    iqs  = (float*)dsm;
    unsigned* keys = dsm + 8 * 256;
    unsigned* hist = keys + 8 * 2048;
    __shared__ unsigned s_prefix[8];
    __shared__ int      s_kr[8];
    __shared__ unsigned s_thr[8];

    const int tid = threadIdx.x;
    const int gid = blockIdx.x;
    const int b = (gid * 8) >> 11;
    const int qbase = (gid * 8) & (S_LEN - 1);
    const int qmax = qbase + 7;

    for (int i = tid; i < 8 * IDX_D; i += 256) {
        int r = i >> 8, c = i & 255;
        iqs[i] = iq[(size_t)(b * S_LEN + qbase + r) * IDX_D + c];
    }
    __syncthreads();

    for (int k = tid; k < S_LEN; k += 256) {
        if (k <= qmax) {
            const float4* ikr = (const float4*)(ik + (size_t)(b * S_LEN + k) * IDX_D);
            float acc[8];
#pragma unroll
            for (int r = 0; r < 8; r++) acc[r] = 0.f;
#pragma unroll 4
            for (int i = 0; i < 64; i++) {
                float4 c = ikr[i];
#pragma unroll
                for (int r = 0; r < 8; r++) {
                    float4 a = ((const float4*)(iqs + r * 256))[i];
                    acc[r] += a.x * c.x + a.y * c.y + a.z * c.z + a.w * c.w;
                }
            }
#pragma unroll
            for (int r = 0; r < 8; r++) {
                unsigned key = 0u;
                if (k <= qbase + r) {
                    unsigned u = __float_as_uint(acc[r]);
                    key = (u & 0x80000000u) ? ~u : (u | 0x80000000u);
                }
                keys[r * S_LEN + k] = key;
            }
        } else {
#pragma unroll
            for (int r = 0; r < 8; r++) keys[r * S_LEN + k] = 0u;
        }
    }

    int topk = topk_ptr ? topk_ptr[0] : 512;
    if (topk > S_LEN) topk = S_LEN;

    const int row  = tid >> 5;
    const int lane = tid & 31;
    const bool active = (qbase + row + 1 > topk);
    if (lane == 0) { s_prefix[row] = 0u; s_kr[row] = topk; }
    __syncthreads();

    for (int pass = 0; pass < 4; pass++) {
        const int shift = 24 - pass * 8;
        for (int i = tid; i < 8 * 256; i += 256) hist[i] = 0u;
        __syncthreads();
        if (active) {
            const unsigned pref = s_prefix[row];
            const unsigned* kr = keys + row * S_LEN;
            for (int k = lane; k < S_LEN; k += 32) {
                unsigned key = kr[k];
                bool match = (pass == 0) || ((key >> (shift + 8)) == (pref >> (shift + 8)));
                if (match) atomicAdd(&hist[row * 256 + ((key >> shift) & 255u)], 1u);
            }
        }
        __syncthreads();
        if (active && lane == 0) {
            int kk = s_kr[row];
            unsigned p = s_prefix[row];
            const unsigned* hr = hist + row * 256;
            for (int d = 255; d >= 0; d--) {
                int c = (int)hr[d];
                if (kk <= c) { s_prefix[row] = p | ((unsigned)d << shift); break; }
                kk -= c;
            }
            s_kr[row] = kk;
        }
        __syncthreads();
    }
    if (lane == 0) s_thr[row] = active ? s_prefix[row] : 0u;
    __syncthreads();

    for (int w = tid; w < 8 * 64; w += 256) {
        int r = w >> 6, wi = w & 63;
        int q = qbase + r;
        unsigned thr = s_thr[r];
        const unsigned* kr = keys + r * S_LEN;
        unsigned word = 0u;
        int kb = wi * 32;
#pragma unroll
        for (int bit = 0; bit < 32; bit++) {
            int k = kb + bit;
            unsigned key = kr[k];
            if (k <= q && key >= thr && key != 0u) word |= (1u << bit);
        }
        mask[(size_t)(b * S_LEN + q) * 64 + wi] = word;
    }
}

// ---------------- fused rope + h/l split flash operand prep (validated) ----------
__global__ void prep_flash_rope(const float* __restrict__ qkv,
                                bf16* __restrict__ qh, bf16* __restrict__ ql,
                                bf16* __restrict__ kh, bf16* __restrict__ kl,
                                bf16* __restrict__ vth, bf16* __restrict__ vtl,
                                int BS)
{
    int idx = blockIdx.x * blockDim.x + threadIdx.x;
    if (idx >= BS * 512) return;
    int i   = idx & 31;
    int h   = (idx >> 5) & 15;
    int tok = idx >> 9;
    int b   = tok >> 11;
    int s   = tok & (S_LEN - 1);

    size_t base = (size_t)tok * 3072 + h * 64 + 2 * i;
    float q1 = qkv[base],        q2 = qkv[base + 1];
    float k1 = qkv[base + 1024], k2 = qkv[base + 1025];
    float v1 = qkv[base + 2048], v2 = qkv[base + 2049];

    float ex   = (float)(2 * i) * (1.0f / 64.0f);
    float freq = powf(10000.0f, -ex);
    float ang  = (float)s * freq;
    float sn, cs;
    sincosf(ang, &sn, &cs);

    float qa = q1 * cs - q2 * sn, qb = q1 * sn + q2 * cs;
    float ka = k1 * cs - k2 * sn, kb = k1 * sn + k2 * cs;

    size_t bh = (size_t)b * N_HEADS + h;
    size_t ro = (bh * S_LEN + s) * 64 + 2 * (size_t)i;
    {
        bf16 hh = __float2bfloat16(qa);
        qh[ro] = hh; ql[ro] = __float2bfloat16(qa - __bfloat162float(hh));
        hh = __float2bfloat16(qb);
        qh[ro + 1] = hh; ql[ro + 1] = __float2bfloat16(qb - __bfloat162float(hh));
    }
    {
        bf16 hh = __float2bfloat16(ka);
        kh[ro] = hh; kl[ro] = __float2bfloat16(ka - __bfloat162float(hh));
        hh = __float2bfloat16(kb);
        kh[ro + 1] = hh; kl[ro + 1] = __float2bfloat16(kb - __bfloat162float(hh));
    }
    {
        size_t vo = (bh * 64 + 2 * (size_t)i) * S_LEN + s;
        bf16 hh = __float2bfloat16(v1);
        vth[vo] = hh; vtl[vo] = __float2bfloat16(v1 - __bfloat162float(hh));
        hh = __float2bfloat16(v2);
        vth[vo + S_LEN] = hh; vtl[vo + S_LEN] = __float2bfloat16(v2 - __bfloat162float(hh));
    }
}

// ---------------- FA2-style tensor-core masked flash (validated core) -----------
// Epilogue now emits attn3 (h,l,h) triples directly (fuses the old split_a pass).
#define KSTR   72
#define KSTRB  144
#define KTILE  (64 * KSTR)
#define FSMEM3 (8 * KTILE * 2)    // 73728 bytes

__device__ __forceinline__ uint32_t pack_bf2(bf16 a, bf16 b) {
    return (uint32_t)__bfloat16_as_ushort(a) |
           ((uint32_t)__bfloat16_as_ushort(b) << 16);
}

__global__ __launch_bounds__(256) void flash_mma3(
    const bf16* __restrict__ qh, const bf16* __restrict__ ql,
    const bf16* __restrict__ kh, const bf16* __restrict__ kl,
    const bf16* __restrict__ vth, const bf16* __restrict__ vtl,
    const unsigned* __restrict__ mask, bf16* __restrict__ attn3)
{
    extern __shared__ __align__(16) bf16 sm[];
    const int tid  = threadIdx.x;
    const int warp = tid >> 5, lane = tid & 31;
    const int qt = gridDim.x - 1 - blockIdx.x;
    const int hd = blockIdx.y, b = blockIdx.z;

    const uint32_t sbase = (uint32_t)__cvta_generic_to_shared(sm);

    const size_t bh = (size_t)b * N_HEADS + hd;
    const bf16* qhg  = qh  + (bh * S_LEN + (size_t)qt * 128) * 64;
    const bf16* qlg  = ql  + (bh * S_LEN + (size_t)qt * 128) * 64;
    const bf16* khg  = kh  + bh * S_LEN * 64;
    const bf16* klg  = kl  + bh * S_LEN * 64;
    const bf16* vthg = vth + bh * 64 * (size_t)S_LEN;
    const bf16* vtlg = vtl + bh * 64 * (size_t)S_LEN;

    const uint32_t QHS = sbase + (4 * KTILE) * 2;
    const uint32_t QLS = sbase + (6 * KTILE) * 2;
    for (int c = tid; c < 2048; c += 256) {
        if (c < 1024) {
            int row = c >> 3, ch = c & 7;
            CP16(QHS + row * KSTRB + ch * 16, qhg + (size_t)row * 64 + ch * 8);
        } else {
            int cc = c - 1024;
            int row = cc >> 3, ch = cc & 7;
            CP16(QLS + row * KSTRB + ch * 16, qlg + (size_t)row * 64 + ch * 8);
        }
    }
    CPCOMMIT();

    for (int c = tid; c < 2048; c += 256) {
        int q4 = c >> 9, idx = c & 511;
        int row = idx >> 3, ch = idx & 7;
        uint32_t dst = sbase + (uint32_t)q4 * (KTILE * 2) + row * KSTRB + ch * 16;
        const bf16* src;
        if      (q4 == 0) src = khg  + (size_t)row * 64 + ch * 8;
        else if (q4 == 1) src = klg  + (size_t)row * 64 + ch * 8;
        else if (q4 == 2) src = vthg + (size_t)row * S_LEN + ch * 8;
        else              src = vtlg + (size_t)row * S_LEN + ch * 8;
        CP16(dst, src);
    }
    CPCOMMIT();
    CPWAIT0();
    __syncthreads();

    uint32_t aQh[4][4], aQl[4][4];
    const uint32_t qro = (uint32_t)((warp * 16 + (lane & 15)) * KSTRB + ((lane >> 4) << 3) * 2);
#pragma unroll
    for (int ks = 0; ks < 4; ks++) {
        ldsm_x4(aQh[ks], QHS + qro + ks * 32);
        ldsm_x4(aQl[ks], QLS + qro + ks * 32);
    }
    __syncthreads();

    float O[8][4];
#pragma unroll
    for (int i = 0; i < 8; i++)
#pragma unroll
        for (int j = 0; j < 4; j++) O[i][j] = 0.f;
    float m0 = -1e30f, m1 = -1e30f, l0 = 0.f, l1 = 0.f;

    const int r0 = warp * 16 + (lane >> 2);
    const int q0 = qt * 128 + r0, q1 = q0 + 8;
    const unsigned* mrow0 = mask + ((size_t)b * S_LEN + q0) * 64;
    const unsigned* mrow1 = mask + ((size_t)b * S_LEN + q1) * 64;

    const int browo = (lane & 7) + ((lane >> 4) << 3);
    const uint32_t bcol = (uint32_t)((((lane >> 3) & 1) << 3) * 2);

    const int ktmax = 2 * qt + 1;

    for (int kt = 0; kt <= ktmax; kt++) {
        const int buf = kt & 1;
        if (kt < ktmax) {
            const uint32_t dbase = sbase + (uint32_t)(buf ^ 1) * (4 * KTILE * 2);
            const size_t kro = (size_t)(kt + 1) * 64;
            for (int c = tid; c < 2048; c += 256) {
                int q4 = c >> 9, idx = c & 511;
                int row = idx >> 3, ch = idx & 7;
                uint32_t dst = dbase + (uint32_t)q4 * (KTILE * 2) + row * KSTRB + ch * 16;
                const bf16* src;
                if      (q4 == 0) src = khg  + (kro + row) * 64 + ch * 8;
                else if (q4 == 1) src = klg  + (kro + row) * 64 + ch * 8;
                else if (q4 == 2) src = vthg + (size_t)row * S_LEN + kro + ch * 8;
                else              src = vtlg + (size_t)row * S_LEN + kro + ch * 8;
                CP16(dst, src);
            }
            CPCOMMIT();
            CPWAIT1();
        } else {
            CPWAIT0();
        }
        __syncthreads();

        const uint32_t tb  = sbase + (uint32_t)buf * (4 * KTILE * 2);
        const uint32_t sKh = tb;
        const uint32_t sKl = tb + KTILE * 2;
        const uint32_t sVh = tb + 2 * KTILE * 2;
        const uint32_t sVl = tb + 3 * KTILE * 2;

        float S_[8][4];
#pragma unroll
        for (int i = 0; i < 8; i++)
#pragma unroll
            for (int j = 0; j < 4; j++) S_[i][j] = 0.f;

#pragma unroll
        for (int ks = 0; ks < 4; ks++) {
#pragma unroll
            for (int nt2 = 0; nt2 < 4; nt2++) {
                const uint32_t ro = (uint32_t)((nt2 * 16 + browo) * KSTRB) + bcol + ks * 32;
                uint32_t bb[4];
                ldsm_x4(bb, sKh + ro);
                mma16816(S_[nt2 * 2],     aQh[ks], bb);
                mma16816(S_[nt2 * 2 + 1], aQh[ks], bb + 2);
                mma16816(S_[nt2 * 2],     aQl[ks], bb);
                mma16816(S_[nt2 * 2 + 1], aQl[ks], bb + 2);
                ldsm_x4(bb, sKl + ro);
                mma16816(S_[nt2 * 2],     aQh[ks], bb);
                mma16816(S_[nt2 * 2 + 1], aQh[ks], bb + 2);
            }
        }

        const unsigned mw00 = mrow0[kt * 2], mw01 = mrow0[kt * 2 + 1];
        const unsigned mw10 = mrow1[kt * 2], mw11 = mrow1[kt * 2 + 1];
        float mx0 = -1e30f, mx1 = -1e30f;
#pragma unroll
        for (int nf = 0; nf < 8; nf++) {
            int c = nf * 8 + 2 * (lane & 3);
#pragma unroll
            for (int e = 0; e < 2; e++) {
                int cc = c + e;
                unsigned w0 = (cc < 32 ? mw00 : mw01) >> (cc & 31);
                unsigned w1 = (cc < 32 ? mw10 : mw11) >> (cc & 31);
                float v0 = (w0 & 1u) ? S_[nf][e] * 0.125f     : -1e30f;
                float v1 = (w1 & 1u) ? S_[nf][e + 2] * 0.125f : -1e30f;
                S_[nf][e] = v0; S_[nf][e + 2] = v1;
                mx0 = fmaxf(mx0, v0); mx1 = fmaxf(mx1, v1);
            }
        }
        mx0 = fmaxf(mx0, __shfl_xor_sync(0xffffffffu, mx0, 1));
        mx0 = fmaxf(mx0, __shfl_xor_sync(0xffffffffu, mx0, 2));
        mx1 = fmaxf(mx1, __shfl_xor_sync(0xffffffffu, mx1, 1));
        mx1 = fmaxf(mx1, __shfl_xor_sync(0xffffffffu, mx1, 2));
        float mn0 = fmaxf(m0, mx0), mn1 = fmaxf(m1, mx1);
        float c0 = __expf(m0 - mn0), c1 = __expf(m1 - mn1);
        float ls0 = 0.f, ls1 = 0.f;
#pragma unroll
        for (int nf = 0; nf < 8; nf++) {
#pragma unroll
            for (int e = 0; e < 2; e++) {
                float p0 = (S_[nf][e]     > -1e29f) ? __expf(S_[nf][e]     - mn0) : 0.f;
                float p1 = (S_[nf][e + 2] > -1e29f) ? __expf(S_[nf][e + 2] - mn1) : 0.f;
                S_[nf][e] = p0; S_[nf][e + 2] = p1;
                ls0 += p0; ls1 += p1;
            }
        }
        ls0 += __shfl_xor_sync(0xffffffffu, ls0, 1);
        ls0 += __shfl_xor_sync(0xffffffffu, ls0, 2);
        ls1 += __shfl_xor_sync(0xffffffffu, ls1, 1);
        ls1 += __shfl_xor_sync(0xffffffffu, ls1, 2);
        l0 = l0 * c0 + ls0; l1 = l1 * c1 + ls1;
        m0 = mn0; m1 = mn1;
#pragma unroll
        for (int nf = 0; nf < 8; nf++) {
            O[nf][0] *= c0; O[nf][1] *= c0;
            O[nf][2] *= c1; O[nf][3] *= c1;
        }

        uint32_t aPh[4][4], aPl[4][4];
#pragma unroll
        for (int ks = 0; ks < 4; ks++) {
#pragma unroll
            for (int half = 0; half < 2; half++) {
                const float* Sf = S_[2 * ks + half];
                bf16 h0 = __float2bfloat16(Sf[0]);
                bf16 l0b = __float2bfloat16(Sf[0] - __bfloat162float(h0));
                bf16 h1 = __float2bfloat16(Sf[1]);
                bf16 l1b = __float2bfloat16(Sf[1] - __bfloat162float(h1));
                bf16 h2 = __float2bfloat16(Sf[2]);
                bf16 l2b = __float2bfloat16(Sf[2] - __bfloat162float(h2));
                bf16 h3 = __float2bfloat16(Sf[3]);
                bf16 l3b = __float2bfloat16(Sf[3] - __bfloat162float(h3));
                aPh[ks][half * 2]     = pack_bf2(h0, h1);
                aPh[ks][half * 2 + 1] = pack_bf2(h2, h3);
                aPl[ks][half * 2]     = pack_bf2(l0b, l1b);
                aPl[ks][half * 2 + 1] = pack_bf2(l2b, l3b);
            }
        }

#pragma unroll
        for (int ks = 0; ks < 4; ks++) {
#pragma unroll
            for (int nt2 = 0; nt2 < 4; nt2++) {
                const uint32_t ro = (uint32_t)((nt2 * 16 + browo) * KSTRB) + bcol + ks * 32;
                uint32_t bb[4];
                ldsm_x4(bb, sVh + ro);
                mma16816(O[nt2 * 2],     aPh[ks], bb);
                mma16816(O[nt2 * 2 + 1], aPh[ks], bb + 2);
                mma16816(O[nt2 * 2],     aPl[ks], bb);
                mma16816(O[nt2 * 2 + 1], aPl[ks], bb + 2);
                ldsm_x4(bb, sVl + ro);
                mma16816(O[nt2 * 2],     aPh[ks], bb);
                mma16816(O[nt2 * 2 + 1], aPh[ks], bb + 2);
            }
        }
        __syncthreads();
    }

    // fused epilogue: normalize and emit attn3 (h,l,h) triples directly
    float inv0 = 1.0f / l0, inv1 = 1.0f / l1;
    bf16* o3r0 = attn3 + ((size_t)b * S_LEN + q0) * 3072;
    bf16* o3r1 = attn3 + ((size_t)b * S_LEN + q1) * 3072;
#pragma unroll
    for (int nf = 0; nf < 8; nf++) {
        int c = nf * 8 + 2 * (lane & 3);
        // row q0: values at cols c, c+1
        {
            float v0 = O[nf][0] * inv0, v1 = O[nf][1] * inv0;
            bf16 h0 = __float2bfloat16(v0);
            bf16 l0b = __float2bfloat16(v0 - __bfloat162float(h0));
            bf16 h1 = __float2bfloat16(v1);
            bf16 l1b = __float2bfloat16(v1 - __bfloat162float(h1));
            uint32_t* p = (uint32_t*)(o3r0 + 3 * (size_t)(hd * 64 + c));
            p[0] = pack_bf2(h0, l0b);
            p[1] = pack_bf2(h0, h1);
            p[2] = pack_bf2(l1b, h1);
        }
        // row q1
        {
            float v0 = O[nf][2] * inv1, v1 = O[nf][3] * inv1;
            bf16 h0 = __float2bfloat16(v0);
            bf16 l0b = __float2bfloat16(v0 - __bfloat162float(h0));
            bf16 h1 = __float2bfloat16(v1);
            bf16 l1b = __float2bfloat16(v1 - __bfloat162float(h1));
            uint32_t* p = (uint32_t*)(o3r1 + 3 * (size_t)(hd * 64 + c));
            p[0] = pack_bf2(h0, l0b);
            p[1] = pack_bf2(h0, h1);
            p[2] = pack_bf2(l1b, h1);
        }
    }
}

// ---------------- launcher with fork/join stream overlap -------------------------
extern "C" void kernel_launch(void* const* d_in, const int* in_sizes, int n_in,
                              void* d_out, int out_size)
{
    static cudaStream_t s_sel = nullptr;
    static cudaEvent_t  ev_fork = nullptr, ev_join = nullptr;
    if (!s_sel) {
        cudaStreamCreateWithFlags(&s_sel, cudaStreamNonBlocking);
        cudaEventCreateWithFlags(&ev_fork, cudaEventDisableTiming);
        cudaEventCreateWithFlags(&ev_join, cudaEventDisableTiming);
    }

    const float* x    = nullptr;
    const float* Wqkv = nullptr;
    const float* Wo   = nullptr;
    const float* Wiq  = nullptr;
    const float* Wik  = nullptr;
    const int*   topk = nullptr;
    for (int i = 0; i < n_in; i++) {
        int sz = in_sizes[i];
        if      (sz == D_MODEL * 3 * D_MODEL)       Wqkv = (const float*)d_in[i];
        else if (sz == D_MODEL * D_MODEL)           Wo   = (const float*)d_in[i];
        else if (sz == D_MODEL * IDX_D) { if (!Wiq) Wiq  = (const float*)d_in[i];
                                          else      Wik  = (const float*)d_in[i]; }
        else if (sz <= 4)                           topk = (const int*)d_in[i];
        else                                        x    = (const float*)d_in[i];
    }

    const int BS = out_size / D_MODEL;
    const int Bn = BS / S_LEN;

    float *qkv, *iq, *ik; unsigned* mask;
    bf16 *x3, *attn3, *wqkv3, *wo3, *qh, *ql, *kh, *kl, *vth, *vtl;
    cudaGetSymbolAddress((void**)&qkv,   g_qkv);
    cudaGetSymbolAddress((void**)&iq,    g_iq);
    cudaGetSymbolAddress((void**)&ik,    g_ik);
    cudaGetSymbolAddress((void**)&mask,  g_mask);
    cudaGetSymbolAddress((void**)&x3,    g_x3);
    cudaGetSymbolAddress((void**)&attn3, g_attn3);
    cudaGetSymbolAddress((void**)&wqkv3, g_wqkv3);
    cudaGetSymbolAddress((void**)&wo3,   g_wo3);
    cudaGetSymbolAddress((void**)&qh,    g_qh);
    cudaGetSymbolAddress((void**)&ql,    g_ql);
    cudaGetSymbolAddress((void**)&kh,    g_kh);
    cudaGetSymbolAddress((void**)&kl,    g_kl);
    cudaGetSymbolAddress((void**)&vth,   g_vth);
    cudaGetSymbolAddress((void**)&vtl,   g_vtl);

    const int K3 = 3 * D_MODEL;
    const int TOPK_SMEM = (8 * 256 + 8 * 2048 + 8 * 256) * 4;

    cudaFuncSetAttribute(mma_gemm, cudaFuncAttributeMaxDynamicSharedMemorySize, GEMM_SMEM);
    cudaFuncSetAttribute(topk8_kernel, cudaFuncAttributeMaxDynamicSharedMemorySize, TOPK_SMEM);
    cudaFuncSetAttribute(flash_mma3, cudaFuncAttributeMaxDynamicSharedMemorySize, FSMEM3);

    // ---- fork: selection chain + Wo weight split on s_sel ----
    cudaEventRecord(ev_fork, 0);
    cudaStreamWaitEvent(s_sel, ev_fork, 0);
    {
        dim3 blk(32, 8);
        split_bT<<<dim3(D_MODEL / 32, D_MODEL / 32), blk, 0, s_sel>>>(Wo, wo3, D_MODEL, D_MODEL);
    }
    sgemm_nn2<<<dim3(IDX_D / 128, BS / 128, 2), 256, 0, s_sel>>>(
        x, Wiq, iq, Wik, ik, BS, IDX_D, D_MODEL);
    topk8_kernel<<<BS / 8, 256, TOPK_SMEM, s_sel>>>(iq, ik, topk, mask);
    cudaEventRecord(ev_join, s_sel);

    // ---- smooth chain on the main (capture) stream ----
    split_a<<<(BS * D_MODEL + 255) / 256, 256>>>(x, x3, BS * D_MODEL);
    {
        dim3 blk(32, 8);
        split_bT<<<dim3(3 * D_MODEL / 32, D_MODEL / 32), blk>>>(Wqkv, wqkv3, D_MODEL, 3 * D_MODEL);
    }
    mma_gemm<<<dim3(3 * D_MODEL / BNg, BS / BMg), 256, GEMM_SMEM>>>(
        x3, wqkv3, qkv, BS, 3 * D_MODEL, K3);
    prep_flash_rope<<<(BS * 512 + 255) / 256, 256>>>(qkv, qh, ql, kh, kl, vth, vtl, BS);

    // ---- join: flash needs the mask (and wo3 for the later Wo gemm) ----
    cudaStreamWaitEvent(0, ev_join, 0);
    flash_mma3<<<dim3(S_LEN / 128, N_HEADS, Bn), 256, FSMEM3>>>(
        qh, ql, kh, kl, vth, vtl, mask, attn3);

    // output projection (reads attn3 written by flash epilogue)
    mma_gemm<<<dim3(D_MODEL / BNg, BS / BMg), 256, GEMM_SMEM>>>(
        attn3, wo3, (float*)d_out, BS, D_MODEL, K3);
}

// round 14
// speedup vs baseline: 1.0125x; 1.0125x over previous
#include <cuda_runtime.h>
#include <cuda_bf16.h>
#include <cstdint>
#include <math.h>

#define S_LEN   2048
#define D_MODEL 1024
#define N_HEADS 16
#define IDX_D   256
#define MAXB    2
#define BS_MAX  (MAXB * S_LEN)

typedef __nv_bfloat16 bf16;

// ---------------- scratch (static device globals; no allocation) ----------------
__device__ float    g_iq  [(size_t)BS_MAX * IDX_D];
__device__ float    g_ik  [(size_t)BS_MAX * IDX_D];
__device__ unsigned g_mask[(size_t)BS_MAX * (S_LEN / 32)];

__device__ __align__(16) bf16 g_x3   [(size_t)BS_MAX * 3 * D_MODEL];
__device__ __align__(16) bf16 g_attn3[(size_t)BS_MAX * 3 * D_MODEL];
__device__ __align__(16) bf16 g_wqkv3[(size_t)(3 * D_MODEL) * 3 * D_MODEL];
__device__ __align__(16) bf16 g_wo3  [(size_t)D_MODEL * 3 * D_MODEL];

// flash operands: h/l split pairs
__device__ __align__(16) bf16 g_qh [(size_t)MAXB * N_HEADS * S_LEN * 64];
__device__ __align__(16) bf16 g_ql [(size_t)MAXB * N_HEADS * S_LEN * 64];
__device__ __align__(16) bf16 g_kh [(size_t)MAXB * N_HEADS * S_LEN * 64];
__device__ __align__(16) bf16 g_kl [(size_t)MAXB * N_HEADS * S_LEN * 64];
__device__ __align__(16) bf16 g_vth[(size_t)MAXB * N_HEADS * 64 * S_LEN];
__device__ __align__(16) bf16 g_vtl[(size_t)MAXB * N_HEADS * 64 * S_LEN];

// ---------------- bf16x3 split conversions --------------------------------------
__global__ void split_a(const float* __restrict__ s, bf16* __restrict__ d, int n)
{
    int i = blockIdx.x * blockDim.x + threadIdx.x;
    if (i >= n) return;
    float v = s[i];
    bf16 h = __float2bfloat16(v);
    bf16 l = __float2bfloat16(v - __bfloat162float(h));
    d[3 * i] = h; d[3 * i + 1] = l; d[3 * i + 2] = h;
}

__global__ void split_bT(const float* __restrict__ W, bf16* __restrict__ out,
                         int K, int N)
{
    __shared__ float t[32][33];
    int n0 = blockIdx.x * 32, k0 = blockIdx.y * 32;
    int tx = threadIdx.x, ty = threadIdx.y;   // block (32,8)
    for (int i = ty; i < 32; i += 8)
        t[i][tx] = W[(size_t)(k0 + i) * N + n0 + tx];
    __syncthreads();
    for (int r = ty; r < 32; r += 8) {
        float v = t[tx][r];
        bf16 h = __float2bfloat16(v);
        bf16 l = __float2bfloat16(v - __bfloat162float(h));
        size_t o = (size_t)(n0 + r) * (3 * K) + 3 * (size_t)(k0 + tx);
        out[o] = h; out[o + 1] = h; out[o + 2] = l;
    }
}

// ---------------- shared mma helpers ---------------------------------------------
#define BMg 128
#define BNg 128
#define BKg 32
#define GEMM_SMEM (3 * (BMg + BNg) * 40 * 2)   // 61440 bytes

__device__ __forceinline__ void ldsm_x4(uint32_t* r, uint32_t a) {
    asm volatile("ldmatrix.sync.aligned.m8n8.x4.shared.b16 {%0,%1,%2,%3}, [%4];"
                 : "=r"(r[0]), "=r"(r[1]), "=r"(r[2]), "=r"(r[3]) : "r"(a));
}
__device__ __forceinline__ void mma16816(float* c, const uint32_t* a, const uint32_t* b) {
    asm volatile("mma.sync.aligned.m16n8k16.row.col.f32.bf16.bf16.f32 "
                 "{%0,%1,%2,%3},{%4,%5,%6,%7},{%8,%9},{%0,%1,%2,%3};"
                 : "+f"(c[0]), "+f"(c[1]), "+f"(c[2]), "+f"(c[3])
                 : "r"(a[0]), "r"(a[1]), "r"(a[2]), "r"(a[3]), "r"(b[0]), "r"(b[1]));
}
#define CP16(sa, ga) asm volatile("cp.async.cg.shared.global [%0], [%1], 16;\n" :: "r"(sa), "l"(ga))
#define CPCOMMIT()   asm volatile("cp.async.commit_group;\n" ::: "memory")
#define CPWAIT0()    asm volatile("cp.async.wait_group 0;\n" ::: "memory")
#define CPWAIT1()    asm volatile("cp.async.wait_group 1;\n" ::: "memory")

__device__ __forceinline__ uint32_t pack_bf2(bf16 a, bf16 b) {
    return (uint32_t)__bfloat16_as_ushort(a) |
           ((uint32_t)__bfloat16_as_ushort(b) << 16);
}

// ---------------- GEMM mainloop body (macro keeps both kernels identical) -------
// Computes acc[4][4][4] for C-tile (by*128, bx*128) of A[M,K3]*B[N,K3]^T.
#define GEMM_BODY(A_, B_, K_)                                                      \
    const uint32_t BUFA  = BMg * 40 * 2;                                           \
    const uint32_t BUFAB = (BMg + BNg) * 40 * 2;                                   \
    const uint32_t sbase = (uint32_t)__cvta_generic_to_shared(gsm);                \
    const uint32_t sA = sbase;                                                     \
    const uint32_t sB = sbase + BUFA;                                              \
    const int ldrow = tid >> 2;                                                    \
    const int ldch  = (tid & 3) * 8;                                               \
    float acc[4][4][4];                                                            \
    _Pragma("unroll")                                                              \
    for (int i = 0; i < 4; i++)                                                    \
        _Pragma("unroll")                                                          \
        for (int j = 0; j < 4; j++)                                                \
            _Pragma("unroll")                                                      \
            for (int t = 0; t < 4; t++) acc[i][j][t] = 0.f;                        \
    const int KT = (K_) / BKg;                                                     \
    _Pragma("unroll")                                                              \
    for (int pf = 0; pf < 2; pf++) {                                               \
        int k0 = pf * BKg;                                                         \
        _Pragma("unroll")                                                          \
        for (int hh = 0; hh < 2; hh++) {                                           \
            int row = ldrow + hh * 64;                                             \
            CP16(sA + pf * BUFAB + (uint32_t)(row * 40 + ldch) * 2,                \
                 (A_) + (size_t)(by * BMg + row) * (K_) + k0 + ldch);              \
            CP16(sB + pf * BUFAB + (uint32_t)(row * 40 + ldch) * 2,                \
                 (B_) + (size_t)(bx * BNg + row) * (K_) + k0 + ldch);              \
        }                                                                          \
        CPCOMMIT();                                                                \
    }                                                                              \
    CPWAIT1();                                                                     \
    __syncthreads();                                                               \
    const int browo = (lane & 7) + ((lane >> 4) << 3);                             \
    const int bkoff = (((lane >> 3) & 1) << 3);                                    \
    for (int kt = 0; kt < KT; kt++) {                                              \
        const uint32_t bo = (uint32_t)(kt % 3) * BUFAB;                            \
        _Pragma("unroll")                                                          \
        for (int ks = 0; ks < BKg; ks += 16) {                                     \
            uint32_t af[4][4], bfr[2][4];                                          \
            const int arow = wm * 64 + (lane & 15);                                \
            const int acol = ks + ((lane >> 4) << 3);                              \
            _Pragma("unroll")                                                      \
            for (int mt = 0; mt < 4; mt++)                                         \
                ldsm_x4(af[mt], sA + bo +                                          \
                        (uint32_t)((arow + mt * 16) * 40 + acol) * 2);             \
            _Pragma("unroll")                                                      \
            for (int nt2 = 0; nt2 < 2; nt2++)                                      \
                ldsm_x4(bfr[nt2], sB + bo +                                        \
                        (uint32_t)((wn * 32 + nt2 * 16 + browo) * 40 + ks + bkoff) * 2); \
            _Pragma("unroll")                                                      \
            for (int mt = 0; mt < 4; mt++)                                         \
                _Pragma("unroll")                                                  \
                for (int nt = 0; nt < 4; nt++)                                     \
                    mma16816(acc[mt][nt], af[mt], bfr[nt >> 1] + (nt & 1) * 2);    \
        }                                                                          \
        __syncthreads();                                                           \
        if (kt + 2 < KT) {                                                         \
            const uint32_t po = (uint32_t)((kt + 2) % 3) * BUFAB;                  \
            const int k0 = (kt + 2) * BKg;                                         \
            _Pragma("unroll")                                                      \
            for (int hh = 0; hh < 2; hh++) {                                       \
                int row = ldrow + hh * 64;                                         \
                CP16(sA + po + (uint32_t)(row * 40 + ldch) * 2,                    \
                     (A_) + (size_t)(by * BMg + row) * (K_) + k0 + ldch);          \
                CP16(sB + po + (uint32_t)(row * 40 + ldch) * 2,                    \
                     (B_) + (size_t)(bx * BNg + row) * (K_) + k0 + ldch);          \
            }                                                                      \
            CPCOMMIT();                                                            \
        }                                                                          \
        if (kt + 1 < KT) {                                                         \
            if (kt + 2 < KT) CPWAIT1(); else CPWAIT0();                            \
            __syncthreads();                                                       \
        }                                                                          \
    }

// ---------------- plain NT GEMM (Wo projection; validated round 13) -------------
__global__ __launch_bounds__(256) void mma_gemm(
    const bf16* __restrict__ A, const bf16* __restrict__ B, float* __restrict__ C,
    int M, int N, int K)
{
    extern __shared__ __align__(16) bf16 gsm[];
    const int bx = blockIdx.x, by = blockIdx.y;
    const int tid  = threadIdx.x;
    const int warp = tid >> 5, lane = tid & 31;
    const int wm = warp & 1, wn = warp >> 1;

    GEMM_BODY(A, B, K)

#pragma unroll
    for (int mt = 0; mt < 4; mt++) {
#pragma unroll
        for (int nt = 0; nt < 4; nt++) {
            int row = by * BMg + wm * 64 + mt * 16 + (lane >> 2);
            int col = bx * BNg + wn * 32 + nt * 8 + (lane & 3) * 2;
            float2 v0 = make_float2(acc[mt][nt][0], acc[mt][nt][1]);
            float2 v1 = make_float2(acc[mt][nt][2], acc[mt][nt][3]);
            *(float2*)&C[(size_t)row * N + col]       = v0;
            *(float2*)&C[(size_t)(row + 8) * N + col] = v1;
        }
    }
}

// ---------------- QKV GEMM with fused rope + h/l-split epilogue -----------------
// Accumulator column pairs (c, c+1), c even == rope pairs (2i, 2i+1).
// Each 128-col block slab is entirely within Q, K or V (1024 % 128 == 0).
__global__ __launch_bounds__(256) void mma_gemm_qkv(
    const bf16* __restrict__ A, const bf16* __restrict__ B,
    bf16* __restrict__ qh, bf16* __restrict__ ql,
    bf16* __restrict__ kh, bf16* __restrict__ kl,
    bf16* __restrict__ vth, bf16* __restrict__ vtl,
    int K)
{
    extern __shared__ __align__(16) bf16 gsm[];
    const int bx = blockIdx.x, by = blockIdx.y;
    const int tid  = threadIdx.x;
    const int warp = tid >> 5, lane = tid & 31;
    const int wm = warp & 1, wn = warp >> 1;

    GEMM_BODY(A, B, K)

    const int part = bx >> 3;                         // 0=Q, 1=K, 2=V
#pragma unroll
    for (int mt = 0; mt < 4; mt++) {
        const int tok0 = by * BMg + wm * 64 + mt * 16 + (lane >> 2);
        const int tok1 = tok0 + 8;
        const int b0 = tok0 >> 11, s0 = tok0 & (S_LEN - 1);
        const int b1 = tok1 >> 11, s1 = tok1 & (S_LEN - 1);
#pragma unroll
        for (int nt = 0; nt < 4; nt++) {
            const int col = bx * BNg + wn * 32 + nt * 8 + (lane & 3) * 2;
            const int pc = col & (D_MODEL - 1);       // col within part
            const int hh = pc >> 6;
            const int d  = pc & 63;                   // even
            float v00 = acc[mt][nt][0], v01 = acc[mt][nt][1];
            float v10 = acc[mt][nt][2], v11 = acc[mt][nt][3];

            if (part < 2) {
                // rope (identical formula to the validated rope path)
                const int i = d >> 1;
                float ex   = (float)(2 * i) * (1.0f / 64.0f);
                float freq = powf(10000.0f, -ex);
                float sn0, cs0, sn1, cs1;
                sincosf((float)s0 * freq, &sn0, &cs0);
                sincosf((float)s1 * freq, &sn1, &cs1);
                float a0 = v00 * cs0 - v01 * sn0, b0v = v00 * sn0 + v01 * cs0;
                float a1 = v10 * cs1 - v11 * sn1, b1v = v10 * sn1 + v11 * cs1;

                bf16* dh = part == 0 ? qh : kh;
                bf16* dl = part == 0 ? ql : kl;
                {
                    size_t ro = (((size_t)b0 * N_HEADS + hh) * S_LEN + s0) * 64 + d;
                    bf16 h0 = __float2bfloat16(a0);
                    bf16 l0 = __float2bfloat16(a0 - __bfloat162float(h0));
                    bf16 h1 = __float2bfloat16(b0v);
                    bf16 l1 = __float2bfloat16(b0v - __bfloat162float(h1));
                    *(uint32_t*)(dh + ro) = pack_bf2(h0, h1);
                    *(uint32_t*)(dl + ro) = pack_bf2(l0, l1);
                }
                {
                    size_t ro = (((size_t)b1 * N_HEADS + hh) * S_LEN + s1) * 64 + d;
                    bf16 h0 = __float2bfloat16(a1);
                    bf16 l0 = __float2bfloat16(a1 - __bfloat162float(h0));
                    bf16 h1 = __float2bfloat16(b1v);
                    bf16 l1 = __float2bfloat16(b1v - __bfloat162float(h1));
                    *(uint32_t*)(dh + ro) = pack_bf2(h0, h1);
                    *(uint32_t*)(dl + ro) = pack_bf2(l0, l1);
                }
            } else {
                // V: transposed [dim][token] layout, no rope
                size_t vo0 = (((size_t)b0 * N_HEADS + hh) * 64 + d) * S_LEN + s0;
                size_t vo1 = (((size_t)b1 * N_HEADS + hh) * 64 + d) * S_LEN + s1;
                bf16 h0 = __float2bfloat16(v00);
                vth[vo0] = h0; vtl[vo0] = __float2bfloat16(v00 - __bfloat162float(h0));
                h0 = __float2bfloat16(v01);
                vth[vo0 + S_LEN] = h0; vtl[vo0 + S_LEN] = __float2bfloat16(v01 - __bfloat162float(h0));
                h0 = __float2bfloat16(v10);
                vth[vo1] = h0; vtl[vo1] = __float2bfloat16(v10 - __bfloat162float(h0));
                h0 = __float2bfloat16(v11);
                vth[vo1 + S_LEN] = h0; vtl[vo1 + S_LEN] = __float2bfloat16(v11 - __bfloat162float(h0));
            }
        }
    }
}

// ---------------- fp32 SGEMM, dual-output (selection path, validated) -----------
__global__ __launch_bounds__(256) void sgemm_nn2(const float* __restrict__ A,
                                                 const float* __restrict__ B1,
                                                 float* __restrict__ C1,
                                                 const float* __restrict__ B2,
                                                 float* __restrict__ C2,
                                                 int M, int N, int K)
{
    const float* B = blockIdx.z ? B2 : B1;
    float*       C = blockIdx.z ? C2 : C1;

    __shared__ float As[2][8][128];
    __shared__ float Bs[2][8][128];

    const int tid = threadIdx.x;
    const int bx = blockIdx.x, by = blockIdx.y;
    const int tx = tid & 15, ty = tid >> 4;

    const int arow = tid >> 1, ak = (tid & 1) * 4;
    const int brow = tid >> 5, bcol = (tid & 31) * 4;

    const float* Ag = A + (size_t)(by * 128 + arow) * K + ak;
    const float* Bg = B + (size_t)brow * N + bx * 128 + bcol;

    float4 af = *(const float4*)Ag;
    float4 bf = *(const float4*)Bg;
    As[0][ak + 0][arow] = af.x;
    As[0][ak + 1][arow] = af.y;
    As[0][ak + 2][arow] = af.z;
    As[0][ak + 3][arow] = af.w;
    *(float4*)&Bs[0][brow][bcol] = bf;
    __syncthreads();

    float acc[8][8];
#pragma unroll
    for (int i = 0; i < 8; i++)
#pragma unroll
        for (int j = 0; j < 8; j++) acc[i][j] = 0.f;

    int buf = 0;
    for (int k0 = 8; k0 <= K; k0 += 8) {
        const bool next = (k0 < K);
        if (next) {
            af = *(const float4*)(Ag + k0);
            bf = *(const float4*)(Bg + (size_t)k0 * N);
        }
#pragma unroll
        for (int kk = 0; kk < 8; kk++) {
            float a[8], b[8];
            *(float4*)&a[0] = *(const float4*)&As[buf][kk][ty * 8];
            *(float4*)&a[4] = *(const float4*)&As[buf][kk][ty * 8 + 4];
            *(float4*)&b[0] = *(const float4*)&Bs[buf][kk][tx * 8];
            *(float4*)&b[4] = *(const float4*)&Bs[buf][kk][tx * 8 + 4];
#pragma unroll
            for (int i = 0; i < 8; i++)
#pragma unroll
                for (int j = 0; j < 8; j++)
                    acc[i][j] += a[i] * b[j];
        }
        if (next) {
            buf ^= 1;
            As[buf][ak + 0][arow] = af.x;
            As[buf][ak + 1][arow] = af.y;
            As[buf][ak + 2][arow] = af.z;
            As[buf][ak + 3][arow] = af.w;
            *(float4*)&Bs[buf][brow][bcol] = bf;
            __syncthreads();
        }
    }

#pragma unroll
    for (int i = 0; i < 8; i++) {
        float* Crow = C + (size_t)(by * 128 + ty * 8 + i) * N + bx * 128 + tx * 8;
        *(float4*)Crow       = make_float4(acc[i][0], acc[i][1], acc[i][2], acc[i][3]);
        *(float4*)(Crow + 4) = make_float4(acc[i][4], acc[i][5], acc[i][6], acc[i][7]);
    }
}

// ---------------- top-k: 8 rows/block, warp-parallel radix (validated) ----------
__global__ __launch_bounds__(256) void topk8_kernel(const float* __restrict__ iq,
                                                    const float* __restrict__ ik,
                                                    const int* __restrict__ topk_ptr,
                                                    unsigned* __restrict__ mask)
{
    extern __shared__ __align__(16) unsigned dsm[];
    float*    iqs  = (float*)dsm;
    unsigned* keys = dsm + 8 * 256;
    unsigned* hist = keys + 8 * 2048;
    __shared__ unsigned s_prefix[8];
    __shared__ int      s_kr[8];
    __shared__ unsigned s_thr[8];

    const int tid = threadIdx.x;
    const int gid = blockIdx.x;
    const int b = (gid * 8) >> 11;
    const int qbase = (gid * 8) & (S_LEN - 1);
    const int qmax = qbase + 7;

    for (int i = tid; i < 8 * IDX_D; i += 256) {
        int r = i >> 8, c = i & 255;
        iqs[i] = iq[(size_t)(b * S_LEN + qbase + r) * IDX_D + c];
    }
    __syncthreads();

    for (int k = tid; k < S_LEN; k += 256) {
        if (k <= qmax) {
            const float4* ikr = (const float4*)(ik + (size_t)(b * S_LEN + k) * IDX_D);
            float acc[8];
#pragma unroll
            for (int r = 0; r < 8; r++) acc[r] = 0.f;
#pragma unroll 4
            for (int i = 0; i < 64; i++) {
                float4 c = ikr[i];
#pragma unroll
                for (int r = 0; r < 8; r++) {
                    float4 a = ((const float4*)(iqs + r * 256))[i];
                    acc[r] += a.x * c.x + a.y * c.y + a.z * c.z + a.w * c.w;
                }
            }
#pragma unroll
            for (int r = 0; r < 8; r++) {
                unsigned key = 0u;
                if (k <= qbase + r) {
                    unsigned u = __float_as_uint(acc[r]);
                    key = (u & 0x80000000u) ? ~u : (u | 0x80000000u);
                }
                keys[r * S_LEN + k] = key;
            }
        } else {
#pragma unroll
            for (int r = 0; r < 8; r++) keys[r * S_LEN + k] = 0u;
        }
    }

    int topk = topk_ptr ? topk_ptr[0] : 512;
    if (topk > S_LEN) topk = S_LEN;

    const int row  = tid >> 5;
    const int lane = tid & 31;
    const bool active = (qbase + row + 1 > topk);
    if (lane == 0) { s_prefix[row] = 0u; s_kr[row] = topk; }
    __syncthreads();

    for (int pass = 0; pass < 4; pass++) {
        const int shift = 24 - pass * 8;
        for (int i = tid; i < 8 * 256; i += 256) hist[i] = 0u;
        __syncthreads();
        if (active) {
            const unsigned pref = s_prefix[row];
            const unsigned* kr = keys + row * S_LEN;
            for (int k = lane; k < S_LEN; k += 32) {
                unsigned key = kr[k];
                bool match = (pass == 0) || ((key >> (shift + 8)) == (pref >> (shift + 8)));
                if (match) atomicAdd(&hist[row * 256 + ((key >> shift) & 255u)], 1u);
            }
        }
        __syncthreads();
        if (active && lane == 0) {
            int kk = s_kr[row];
            unsigned p = s_prefix[row];
            const unsigned* hr = hist + row * 256;
            for (int d = 255; d >= 0; d--) {
                int c = (int)hr[d];
                if (kk <= c) { s_prefix[row] = p | ((unsigned)d << shift); break; }
                kk -= c;
            }
            s_kr[row] = kk;
        }
        __syncthreads();
    }
    if (lane == 0) s_thr[row] = active ? s_prefix[row] : 0u;
    __syncthreads();

    for (int w = tid; w < 8 * 64; w += 256) {
        int r = w >> 6, wi = w & 63;
        int q = qbase + r;
        unsigned thr = s_thr[r];
        const unsigned* kr = keys + r * S_LEN;
        unsigned word = 0u;
        int kb = wi * 32;
#pragma unroll
        for (int bit = 0; bit < 32; bit++) {
            int k = kb + bit;
            unsigned key = kr[k];
            if (k <= q && key >= thr && key != 0u) word |= (1u << bit);
        }
        mask[(size_t)(b * S_LEN + q) * 64 + wi] = word;
    }
}

// ---------------- FA2-style tensor-core masked flash (validated round 13) -------
#define KSTR   72
#define KSTRB  144
#define KTILE  (64 * KSTR)
#define FSMEM3 (8 * KTILE * 2)    // 73728 bytes

__global__ __launch_bounds__(256) void flash_mma3(
    const bf16* __restrict__ qh, const bf16* __restrict__ ql,
    const bf16* __restrict__ kh, const bf16* __restrict__ kl,
    const bf16* __restrict__ vth, const bf16* __restrict__ vtl,
    const unsigned* __restrict__ mask, bf16* __restrict__ attn3)
{
    extern __shared__ __align__(16) bf16 sm[];
    const int tid  = threadIdx.x;
    const int warp = tid >> 5, lane = tid & 31;
    const int qt = gridDim.x - 1 - blockIdx.x;
    const int hd = blockIdx.y, b = blockIdx.z;

    const uint32_t sbase = (uint32_t)__cvta_generic_to_shared(sm);

    const size_t bh = (size_t)b * N_HEADS + hd;
    const bf16* qhg  = qh  + (bh * S_LEN + (size_t)qt * 128) * 64;
    const bf16* qlg  = ql  + (bh * S_LEN + (size_t)qt * 128) * 64;
    const bf16* khg  = kh  + bh * S_LEN * 64;
    const bf16* klg  = kl  + bh * S_LEN * 64;
    const bf16* vthg = vth + bh * 64 * (size_t)S_LEN;
    const bf16* vtlg = vtl + bh * 64 * (size_t)S_LEN;

    const uint32_t QHS = sbase + (4 * KTILE) * 2;
    const uint32_t QLS = sbase + (6 * KTILE) * 2;
    for (int c = tid; c < 2048; c += 256) {
        if (c < 1024) {
            int row = c >> 3, ch = c & 7;
            CP16(QHS + row * KSTRB + ch * 16, qhg + (size_t)row * 64 + ch * 8);
        } else {
            int cc = c - 1024;
            int row = cc >> 3, ch = cc & 7;
            CP16(QLS + row * KSTRB + ch * 16, qlg + (size_t)row * 64 + ch * 8);
        }
    }
    CPCOMMIT();

    for (int c = tid; c < 2048; c += 256) {
        int q4 = c >> 9, idx = c & 511;
        int row = idx >> 3, ch = idx & 7;
        uint32_t dst = sbase + (uint32_t)q4 * (KTILE * 2) + row * KSTRB + ch * 16;
        const bf16* src;
        if      (q4 == 0) src = khg  + (size_t)row * 64 + ch * 8;
        else if (q4 == 1) src = klg  + (size_t)row * 64 + ch * 8;
        else if (q4 == 2) src = vthg + (size_t)row * S_LEN + ch * 8;
        else              src = vtlg + (size_t)row * S_LEN + ch * 8;
        CP16(dst, src);
    }
    CPCOMMIT();
    CPWAIT0();
    __syncthreads();

    uint32_t aQh[4][4], aQl[4][4];
    const uint32_t qro = (uint32_t)((warp * 16 + (lane & 15)) * KSTRB + ((lane >> 4) << 3) * 2);
#pragma unroll
    for (int ks = 0; ks < 4; ks++) {
        ldsm_x4(aQh[ks], QHS + qro + ks * 32);
        ldsm_x4(aQl[ks], QLS + qro + ks * 32);
    }
    __syncthreads();

    float O[8][4];
#pragma unroll
    for (int i = 0; i < 8; i++)
#pragma unroll
        for (int j = 0; j < 4; j++) O[i][j] = 0.f;
    float m0 = -1e30f, m1 = -1e30f, l0 = 0.f, l1 = 0.f;

    const int r0 = warp * 16 + (lane >> 2);
    const int q0 = qt * 128 + r0, q1 = q0 + 8;
    const unsigned* mrow0 = mask + ((size_t)b * S_LEN + q0) * 64;
    const unsigned* mrow1 = mask + ((size_t)b * S_LEN + q1) * 64;

    const int browo = (lane & 7) + ((lane >> 4) << 3);
    const uint32_t bcol = (uint32_t)((((lane >> 3) & 1) << 3) * 2);

    const int ktmax = 2 * qt + 1;

    for (int kt = 0; kt <= ktmax; kt++) {
        const int buf = kt & 1;
        if (kt < ktmax) {
            const uint32_t dbase = sbase + (uint32_t)(buf ^ 1) * (4 * KTILE * 2);
            const size_t kro = (size_t)(kt + 1) * 64;
            for (int c = tid; c < 2048; c += 256) {
                int q4 = c >> 9, idx = c & 511;
                int row = idx >> 3, ch = idx & 7;
                uint32_t dst = dbase + (uint32_t)q4 * (KTILE * 2) + row * KSTRB + ch * 16;
                const bf16* src;
                if      (q4 == 0) src = khg  + (kro + row) * 64 + ch * 8;
                else if (q4 == 1) src = klg  + (kro + row) * 64 + ch * 8;
                else if (q4 == 2) src = vthg + (size_t)row * S_LEN + kro + ch * 8;
                else              src = vtlg + (size_t)row * S_LEN + kro + ch * 8;
                CP16(dst, src);
            }
            CPCOMMIT();
            CPWAIT1();
        } else {
            CPWAIT0();
        }
        __syncthreads();

        const uint32_t tb  = sbase + (uint32_t)buf * (4 * KTILE * 2);
        const uint32_t sKh = tb;
        const uint32_t sKl = tb + KTILE * 2;
        const uint32_t sVh = tb + 2 * KTILE * 2;
        const uint32_t sVl = tb + 3 * KTILE * 2;

        float S_[8][4];
#pragma unroll
        for (int i = 0; i < 8; i++)
#pragma unroll
            for (int j = 0; j < 4; j++) S_[i][j] = 0.f;

#pragma unroll
        for (int ks = 0; ks < 4; ks++) {
#pragma unroll
            for (int nt2 = 0; nt2 < 4; nt2++) {
                const uint32_t ro = (uint32_t)((nt2 * 16 + browo) * KSTRB) + bcol + ks * 32;
                uint32_t bb[4];
                ldsm_x4(bb, sKh + ro);
                mma16816(S_[nt2 * 2],     aQh[ks], bb);
                mma16816(S_[nt2 * 2 + 1], aQh[ks], bb + 2);
                mma16816(S_[nt2 * 2],     aQl[ks], bb);
                mma16816(S_[nt2 * 2 + 1], aQl[ks], bb + 2);
                ldsm_x4(bb, sKl + ro);
                mma16816(S_[nt2 * 2],     aQh[ks], bb);
                mma16816(S_[nt2 * 2 + 1], aQh[ks], bb + 2);
            }
        }

        const unsigned mw00 = mrow0[kt * 2], mw01 = mrow0[kt * 2 + 1];
        const unsigned mw10 = mrow1[kt * 2], mw11 = mrow1[kt * 2 + 1];
        float mx0 = -1e30f, mx1 = -1e30f;
#pragma unroll
        for (int nf = 0; nf < 8; nf++) {
            int c = nf * 8 + 2 * (lane & 3);
#pragma unroll
            for (int e = 0; e < 2; e++) {
                int cc = c + e;
                unsigned w0 = (cc < 32 ? mw00 : mw01) >> (cc & 31);
                unsigned w1 = (cc < 32 ? mw10 : mw11) >> (cc & 31);
                float v0 = (w0 & 1u) ? S_[nf][e] * 0.125f     : -1e30f;
                float v1 = (w1 & 1u) ? S_[nf][e + 2] * 0.125f : -1e30f;
                S_[nf][e] = v0; S_[nf][e + 2] = v1;
                mx0 = fmaxf(mx0, v0); mx1 = fmaxf(mx1, v1);
            }
        }
        mx0 = fmaxf(mx0, __shfl_xor_sync(0xffffffffu, mx0, 1));
        mx0 = fmaxf(mx0, __shfl_xor_sync(0xffffffffu, mx0, 2));
        mx1 = fmaxf(mx1, __shfl_xor_sync(0xffffffffu, mx1, 1));
        mx1 = fmaxf(mx1, __shfl_xor_sync(0xffffffffu, mx1, 2));
        float mn0 = fmaxf(m0, mx0), mn1 = fmaxf(m1, mx1);
        float c0 = __expf(m0 - mn0), c1 = __expf(m1 - mn1);
        float ls0 = 0.f, ls1 = 0.f;
#pragma unroll
        for (int nf = 0; nf < 8; nf++) {
#pragma unroll
            for (int e = 0; e < 2; e++) {
                float p0 = (S_[nf][e]     > -1e29f) ? __expf(S_[nf][e]     - mn0) : 0.f;
                float p1 = (S_[nf][e + 2] > -1e29f) ? __expf(S_[nf][e + 2] - mn1) : 0.f;
                S_[nf][e] = p0; S_[nf][e + 2] = p1;
                ls0 += p0; ls1 += p1;
            }
        }
        ls0 += __shfl_xor_sync(0xffffffffu, ls0, 1);
        ls0 += __shfl_xor_sync(0xffffffffu, ls0, 2);
        ls1 += __shfl_xor_sync(0xffffffffu, ls1, 1);
        ls1 += __shfl_xor_sync(0xffffffffu, ls1, 2);
        l0 = l0 * c0 + ls0; l1 = l1 * c1 + ls1;
        m0 = mn0; m1 = mn1;
#pragma unroll
        for (int nf = 0; nf < 8; nf++) {
            O[nf][0] *= c0; O[nf][1] *= c0;
            O[nf][2] *= c1; O[nf][3] *= c1;
        }

        uint32_t aPh[4][4], aPl[4][4];
#pragma unroll
        for (int ks = 0; ks < 4; ks++) {
#pragma unroll
            for (int half = 0; half < 2; half++) {
                const float* Sf = S_[2 * ks + half];
                bf16 h0 = __float2bfloat16(Sf[0]);
                bf16 l0b = __float2bfloat16(Sf[0] - __bfloat162float(h0));
                bf16 h1 = __float2bfloat16(Sf[1]);
                bf16 l1b = __float2bfloat16(Sf[1] - __bfloat162float(h1));
                bf16 h2 = __float2bfloat16(Sf[2]);
                bf16 l2b = __float2bfloat16(Sf[2] - __bfloat162float(h2));
                bf16 h3 = __float2bfloat16(Sf[3]);
                bf16 l3b = __float2bfloat16(Sf[3] - __bfloat162float(h3));
                aPh[ks][half * 2]     = pack_bf2(h0, h1);
                aPh[ks][half * 2 + 1] = pack_bf2(h2, h3);
                aPl[ks][half * 2]     = pack_bf2(l0b, l1b);
                aPl[ks][half * 2 + 1] = pack_bf2(l2b, l3b);
            }
        }

#pragma unroll
        for (int ks = 0; ks < 4; ks++) {
#pragma unroll
            for (int nt2 = 0; nt2 < 4; nt2++) {
                const uint32_t ro = (uint32_t)((nt2 * 16 + browo) * KSTRB) + bcol + ks * 32;
                uint32_t bb[4];
                ldsm_x4(bb, sVh + ro);
                mma16816(O[nt2 * 2],     aPh[ks], bb);
                mma16816(O[nt2 * 2 + 1], aPh[ks], bb + 2);
                mma16816(O[nt2 * 2],     aPl[ks], bb);
                mma16816(O[nt2 * 2 + 1], aPl[ks], bb + 2);
                ldsm_x4(bb, sVl + ro);
                mma16816(O[nt2 * 2],     aPh[ks], bb);
                mma16816(O[nt2 * 2 + 1], aPh[ks], bb + 2);
            }
        }
        __syncthreads();
    }

    // fused epilogue: normalize and emit attn3 (h,l,h) triples directly
    float inv0 = 1.0f / l0, inv1 = 1.0f / l1;
    bf16* o3r0 = attn3 + ((size_t)b * S_LEN + q0) * 3072;
    bf16* o3r1 = attn3 + ((size_t)b * S_LEN + q1) * 3072;
#pragma unroll
    for (int nf = 0; nf < 8; nf++) {
        int c = nf * 8 + 2 * (lane & 3);
        {
            float v0 = O[nf][0] * inv0, v1 = O[nf][1] * inv0;
            bf16 h0 = __float2bfloat16(v0);
            bf16 l0b = __float2bfloat16(v0 - __bfloat162float(h0));
            bf16 h1 = __float2bfloat16(v1);
            bf16 l1b = __float2bfloat16(v1 - __bfloat162float(h1));
            uint32_t* p = (uint32_t*)(o3r0 + 3 * (size_t)(hd * 64 + c));
            p[0] = pack_bf2(h0, l0b);
            p[1] = pack_bf2(h0, h1);
            p[2] = pack_bf2(l1b, h1);
        }
        {
            float v0 = O[nf][2] * inv1, v1 = O[nf][3] * inv1;
            bf16 h0 = __float2bfloat16(v0);
            bf16 l0b = __float2bfloat16(v0 - __bfloat162float(h0));
            bf16 h1 = __float2bfloat16(v1);
            bf16 l1b = __float2bfloat16(v1 - __bfloat162float(h1));
            uint32_t* p = (uint32_t*)(o3r1 + 3 * (size_t)(hd * 64 + c));
            p[0] = pack_bf2(h0, l0b);
            p[1] = pack_bf2(h0, h1);
            p[2] = pack_bf2(l1b, h1);
        }
    }
}

// ---------------- launcher with fork/join stream overlap -------------------------
extern "C" void kernel_launch(void* const* d_in, const int* in_sizes, int n_in,
                              void* d_out, int out_size)
{
    static cudaStream_t s_sel = nullptr;
    static cudaEvent_t  ev_fork = nullptr, ev_join = nullptr, ev_w = nullptr;
    if (!s_sel) {
        cudaStreamCreateWithFlags(&s_sel, cudaStreamNonBlocking);
        cudaEventCreateWithFlags(&ev_fork, cudaEventDisableTiming);
        cudaEventCreateWithFlags(&ev_join, cudaEventDisableTiming);
        cudaEventCreateWithFlags(&ev_w, cudaEventDisableTiming);
    }

    const float* x    = nullptr;
    const float* Wqkv = nullptr;
    const float* Wo   = nullptr;
    const float* Wiq  = nullptr;
    const float* Wik  = nullptr;
    const int*   topk = nullptr;
    for (int i = 0; i < n_in; i++) {
        int sz = in_sizes[i];
        if      (sz == D_MODEL * 3 * D_MODEL)       Wqkv = (const float*)d_in[i];
        else if (sz == D_MODEL * D_MODEL)           Wo   = (const float*)d_in[i];
        else if (sz == D_MODEL * IDX_D) { if (!Wiq) Wiq  = (const float*)d_in[i];
                                          else      Wik  = (const float*)d_in[i]; }
        else if (sz <= 4)                           topk = (const int*)d_in[i];
        else                                        x    = (const float*)d_in[i];
    }

    const int BS = out_size / D_MODEL;
    const int Bn = BS / S_LEN;

    float *iq, *ik; unsigned* mask;
    bf16 *x3, *attn3, *wqkv3, *wo3, *qh, *ql, *kh, *kl, *vth, *vtl;
    cudaGetSymbolAddress((void**)&iq,    g_iq);
    cudaGetSymbolAddress((void**)&ik,    g_ik);
    cudaGetSymbolAddress((void**)&mask,  g_mask);
    cudaGetSymbolAddress((void**)&x3,    g_x3);
    cudaGetSymbolAddress((void**)&attn3, g_attn3);
    cudaGetSymbolAddress((void**)&wqkv3, g_wqkv3);
    cudaGetSymbolAddress((void**)&wo3,   g_wo3);
    cudaGetSymbolAddress((void**)&qh,    g_qh);
    cudaGetSymbolAddress((void**)&ql,    g_ql);
    cudaGetSymbolAddress((void**)&kh,    g_kh);
    cudaGetSymbolAddress((void**)&kl,    g_kl);
    cudaGetSymbolAddress((void**)&vth,   g_vth);
    cudaGetSymbolAddress((void**)&vtl,   g_vtl);

    const int K3 = 3 * D_MODEL;
    const int TOPK_SMEM = (8 * 256 + 8 * 2048 + 8 * 256) * 4;

    cudaFuncSetAttribute(mma_gemm, cudaFuncAttributeMaxDynamicSharedMemorySize, GEMM_SMEM);
    cudaFuncSetAttribute(mma_gemm_qkv, cudaFuncAttributeMaxDynamicSharedMemorySize, GEMM_SMEM);
    cudaFuncSetAttribute(topk8_kernel, cudaFuncAttributeMaxDynamicSharedMemorySize, TOPK_SMEM);
    cudaFuncSetAttribute(flash_mma3, cudaFuncAttributeMaxDynamicSharedMemorySize, FSMEM3);

    // ---- fork: weight splits + selection chain on s_sel ----
    cudaEventRecord(ev_fork, 0);
    cudaStreamWaitEvent(s_sel, ev_fork, 0);
    {
        dim3 blk(32, 8);
        split_bT<<<dim3(3 * D_MODEL / 32, D_MODEL / 32), blk, 0, s_sel>>>(Wqkv, wqkv3, D_MODEL, 3 * D_MODEL);
        cudaEventRecord(ev_w, s_sel);
        split_bT<<<dim3(D_MODEL / 32, D_MODEL / 32), blk, 0, s_sel>>>(Wo, wo3, D_MODEL, D_MODEL);
    }
    sgemm_nn2<<<dim3(IDX_D / 128, BS / 128, 2), 256, 0, s_sel>>>(
        x, Wiq, iq, Wik, ik, BS, IDX_D, D_MODEL);
    topk8_kernel<<<BS / 8, 256, TOPK_SMEM, s_sel>>>(iq, ik, topk, mask);
    cudaEventRecord(ev_join, s_sel);

    // ---- smooth chain on the main (capture) stream ----
    split_a<<<(BS * D_MODEL + 255) / 256, 256>>>(x, x3, BS * D_MODEL);
    cudaStreamWaitEvent(0, ev_w, 0);
    mma_gemm_qkv<<<dim3(3 * D_MODEL / BNg, BS / BMg), 256, GEMM_SMEM>>>(
        x3, wqkv3, qh, ql, kh, kl, vth, vtl, K3);

    // ---- join: flash needs the mask ----
    cudaStreamWaitEvent(0, ev_join, 0);
    flash_mma3<<<dim3(S_LEN / 128, N_HEADS, Bn), 256, FSMEM3>>>(
        qh, ql, kh, kl, vth, vtl, mask, attn3);

    // output projection (reads attn3 written by flash epilogue)
    mma_gemm<<<dim3(D_MODEL / BNg, BS / BMg), 256, GEMM_SMEM>>>(
        attn3, wo3, (float*)d_out, BS, D_MODEL, K3);
}

// round 15
// speedup vs baseline: 1.0943x; 1.0807x over previous
#include <cuda_runtime.h>
#include <cuda_bf16.h>
#include <cstdint>
#include <math.h>

#define S_LEN   2048
#define D_MODEL 1024
#define N_HEADS 16
#define IDX_D   256
#define MAXB    2
#define BS_MAX  (MAXB * S_LEN)

typedef __nv_bfloat16 bf16;

// ---------------- scratch (static device globals; no allocation) ----------------
__device__ float    g_iq  [(size_t)BS_MAX * IDX_D];
__device__ float    g_ik  [(size_t)BS_MAX * IDX_D];
__device__ unsigned g_mask[(size_t)BS_MAX * (S_LEN / 32)];

__device__ __align__(16) bf16 g_x3   [(size_t)BS_MAX * 3 * D_MODEL];
__device__ __align__(16) bf16 g_attn3[(size_t)BS_MAX * 3 * D_MODEL];
__device__ __align__(16) bf16 g_wqkv3[(size_t)(3 * D_MODEL) * 3 * D_MODEL];
__device__ __align__(16) bf16 g_wo3  [(size_t)D_MODEL * 3 * D_MODEL];

// flash operands: h/l split pairs
__device__ __align__(16) bf16 g_qh [(size_t)MAXB * N_HEADS * S_LEN * 64];
__device__ __align__(16) bf16 g_ql [(size_t)MAXB * N_HEADS * S_LEN * 64];
__device__ __align__(16) bf16 g_kh [(size_t)MAXB * N_HEADS * S_LEN * 64];
__device__ __align__(16) bf16 g_kl [(size_t)MAXB * N_HEADS * S_LEN * 64];
__device__ __align__(16) bf16 g_vth[(size_t)MAXB * N_HEADS * 64 * S_LEN];
__device__ __align__(16) bf16 g_vtl[(size_t)MAXB * N_HEADS * 64 * S_LEN];

// ---------------- bf16x3 split conversions --------------------------------------
__global__ void split_a(const float* __restrict__ s, bf16* __restrict__ d, int n)
{
    int i = blockIdx.x * blockDim.x + threadIdx.x;
    if (i >= n) return;
    float v = s[i];
    bf16 h = __float2bfloat16(v);
    bf16 l = __float2bfloat16(v - __bfloat162float(h));
    d[3 * i] = h; d[3 * i + 1] = l; d[3 * i + 2] = h;
}

__global__ void split_bT(const float* __restrict__ W, bf16* __restrict__ out,
                         int K, int N)
{
    __shared__ float t[32][33];
    int n0 = blockIdx.x * 32, k0 = blockIdx.y * 32;
    int tx = threadIdx.x, ty = threadIdx.y;   // block (32,8)
    for (int i = ty; i < 32; i += 8)
        t[i][tx] = W[(size_t)(k0 + i) * N + n0 + tx];
    __syncthreads();
    for (int r = ty; r < 32; r += 8) {
        float v = t[tx][r];
        bf16 h = __float2bfloat16(v);
        bf16 l = __float2bfloat16(v - __bfloat162float(h));
        size_t o = (size_t)(n0 + r) * (3 * K) + 3 * (size_t)(k0 + tx);
        out[o] = h; out[o + 1] = h; out[o + 2] = l;
    }
}

// ---------------- shared mma helpers ---------------------------------------------
#define BMg 128
#define BNg 128
#define BKg 32
#define GEMM_SMEM (3 * (BMg + BNg) * 40 * 2)   // 61440 bytes

__device__ __forceinline__ void ldsm_x4(uint32_t* r, uint32_t a) {
    asm volatile("ldmatrix.sync.aligned.m8n8.x4.shared.b16 {%0,%1,%2,%3}, [%4];"
                 : "=r"(r[0]), "=r"(r[1]), "=r"(r[2]), "=r"(r[3]) : "r"(a));
}
__device__ __forceinline__ void mma16816(float* c, const uint32_t* a, const uint32_t* b) {
    asm volatile("mma.sync.aligned.m16n8k16.row.col.f32.bf16.bf16.f32 "
                 "{%0,%1,%2,%3},{%4,%5,%6,%7},{%8,%9},{%0,%1,%2,%3};"
                 : "+f"(c[0]), "+f"(c[1]), "+f"(c[2]), "+f"(c[3])
                 : "r"(a[0]), "r"(a[1]), "r"(a[2]), "r"(a[3]), "r"(b[0]), "r"(b[1]));
}
#define CP16(sa, ga) asm volatile("cp.async.cg.shared.global [%0], [%1], 16;\n" :: "r"(sa), "l"(ga))
#define CPCOMMIT()   asm volatile("cp.async.commit_group;\n" ::: "memory")
#define CPWAIT0()    asm volatile("cp.async.wait_group 0;\n" ::: "memory")
#define CPWAIT1()    asm volatile("cp.async.wait_group 1;\n" ::: "memory")

__device__ __forceinline__ uint32_t pack_bf2(bf16 a, bf16 b) {
    return (uint32_t)__bfloat16_as_ushort(a) |
           ((uint32_t)__bfloat16_as_ushort(b) << 16);
}

// ---------------- GEMM mainloop body (macro keeps both kernels identical) -------
#define GEMM_BODY(A_, B_, K_)                                                      \
    const uint32_t BUFA  = BMg * 40 * 2;                                           \
    const uint32_t BUFAB = (BMg + BNg) * 40 * 2;                                   \
    const uint32_t sbase = (uint32_t)__cvta_generic_to_shared(gsm);                \
    const uint32_t sA = sbase;                                                     \
    const uint32_t sB = sbase + BUFA;                                              \
    const int ldrow = tid >> 2;                                                    \
    const int ldch  = (tid & 3) * 8;                                               \
    float acc[4][4][4];                                                            \
    _Pragma("unroll")                                                              \
    for (int i = 0; i < 4; i++)                                                    \
        _Pragma("unroll")                                                          \
        for (int j = 0; j < 4; j++)                                                \
            _Pragma("unroll")                                                      \
            for (int t = 0; t < 4; t++) acc[i][j][t] = 0.f;                        \
    const int KT = (K_) / BKg;                                                     \
    _Pragma("unroll")                                                              \
    for (int pf = 0; pf < 2; pf++) {                                               \
        int k0 = pf * BKg;                                                         \
        _Pragma("unroll")                                                          \
        for (int hh = 0; hh < 2; hh++) {                                           \
            int row = ldrow + hh * 64;                                             \
            CP16(sA + pf * BUFAB + (uint32_t)(row * 40 + ldch) * 2,                \
                 (A_) + (size_t)(by * BMg + row) * (K_) + k0 + ldch);              \
            CP16(sB + pf * BUFAB + (uint32_t)(row * 40 + ldch) * 2,                \
                 (B_) + (size_t)(bx * BNg + row) * (K_) + k0 + ldch);              \
        }                                                                          \
        CPCOMMIT();                                                                \
    }                                                                              \
    CPWAIT1();                                                                     \
    __syncthreads();                                                               \
    const int browo = (lane & 7) + ((lane >> 4) << 3);                             \
    const int bkoff = (((lane >> 3) & 1) << 3);                                    \
    for (int kt = 0; kt < KT; kt++) {                                              \
        const uint32_t bo = (uint32_t)(kt % 3) * BUFAB;                            \
        _Pragma("unroll")                                                          \
        for (int ks = 0; ks < BKg; ks += 16) {                                     \
            uint32_t af[4][4], bfr[2][4];                                          \
            const int arow = wm * 64 + (lane & 15);                                \
            const int acol = ks + ((lane >> 4) << 3);                              \
            _Pragma("unroll")                                                      \
            for (int mt = 0; mt < 4; mt++)                                         \
                ldsm_x4(af[mt], sA + bo +                                          \
                        (uint32_t)((arow + mt * 16) * 40 + acol) * 2);             \
            _Pragma("unroll")                                                      \
            for (int nt2 = 0; nt2 < 2; nt2++)                                      \
                ldsm_x4(bfr[nt2], sB + bo +                                        \
                        (uint32_t)((wn * 32 + nt2 * 16 + browo) * 40 + ks + bkoff) * 2); \
            _Pragma("unroll")                                                      \
            for (int mt = 0; mt < 4; mt++)                                         \
                _Pragma("unroll")                                                  \
                for (int nt = 0; nt < 4; nt++)                                     \
                    mma16816(acc[mt][nt], af[mt], bfr[nt >> 1] + (nt & 1) * 2);    \
        }                                                                          \
        __syncthreads();                                                           \
        if (kt + 2 < KT) {                                                         \
            const uint32_t po = (uint32_t)((kt + 2) % 3) * BUFAB;                  \
            const int k0 = (kt + 2) * BKg;                                         \
            _Pragma("unroll")                                                      \
            for (int hh = 0; hh < 2; hh++) {                                       \
                int row = ldrow + hh * 64;                                         \
                CP16(sA + po + (uint32_t)(row * 40 + ldch) * 2,                    \
                     (A_) + (size_t)(by * BMg + row) * (K_) + k0 + ldch);          \
                CP16(sB + po + (uint32_t)(row * 40 + ldch) * 2,                    \
                     (B_) + (size_t)(bx * BNg + row) * (K_) + k0 + ldch);          \
            }                                                                      \
            CPCOMMIT();                                                            \
        }                                                                          \
        if (kt + 1 < KT) {                                                         \
            if (kt + 2 < KT) CPWAIT1(); else CPWAIT0();                            \
            __syncthreads();                                                       \
        }                                                                          \
    }

// ---------------- plain NT GEMM (Wo projection; validated) ----------------------
__global__ __launch_bounds__(256) void mma_gemm(
    const bf16* __restrict__ A, const bf16* __restrict__ B, float* __restrict__ C,
    int M, int N, int K)
{
    extern __shared__ __align__(16) bf16 gsm[];
    const int bx = blockIdx.x, by = blockIdx.y;
    const int tid  = threadIdx.x;
    const int warp = tid >> 5, lane = tid & 31;
    const int wm = warp & 1, wn = warp >> 1;

    GEMM_BODY(A, B, K)

#pragma unroll
    for (int mt = 0; mt < 4; mt++) {
#pragma unroll
        for (int nt = 0; nt < 4; nt++) {
            int row = by * BMg + wm * 64 + mt * 16 + (lane >> 2);
            int col = bx * BNg + wn * 32 + nt * 8 + (lane & 3) * 2;
            float2 v0 = make_float2(acc[mt][nt][0], acc[mt][nt][1]);
            float2 v1 = make_float2(acc[mt][nt][2], acc[mt][nt][3]);
            *(float2*)&C[(size_t)row * N + col]       = v0;
            *(float2*)&C[(size_t)(row + 8) * N + col] = v1;
        }
    }
}

// ---------------- QKV GEMM with fused rope + h/l-split epilogue (validated) -----
__global__ __launch_bounds__(256) void mma_gemm_qkv(
    const bf16* __restrict__ A, const bf16* __restrict__ B,
    bf16* __restrict__ qh, bf16* __restrict__ ql,
    bf16* __restrict__ kh, bf16* __restrict__ kl,
    bf16* __restrict__ vth, bf16* __restrict__ vtl,
    int K)
{
    extern __shared__ __align__(16) bf16 gsm[];
    const int bx = blockIdx.x, by = blockIdx.y;
    const int tid  = threadIdx.x;
    const int warp = tid >> 5, lane = tid & 31;
    const int wm = warp & 1, wn = warp >> 1;

    GEMM_BODY(A, B, K)

    const int part = bx >> 3;                         // 0=Q, 1=K, 2=V
#pragma unroll
    for (int mt = 0; mt < 4; mt++) {
        const int tok0 = by * BMg + wm * 64 + mt * 16 + (lane >> 2);
        const int tok1 = tok0 + 8;
        const int b0 = tok0 >> 11, s0 = tok0 & (S_LEN - 1);
        const int b1 = tok1 >> 11, s1 = tok1 & (S_LEN - 1);
#pragma unroll
        for (int nt = 0; nt < 4; nt++) {
            const int col = bx * BNg + wn * 32 + nt * 8 + (lane & 3) * 2;
            const int pc = col & (D_MODEL - 1);
            const int hh = pc >> 6;
            const int d  = pc & 63;
            float v00 = acc[mt][nt][0], v01 = acc[mt][nt][1];
            float v10 = acc[mt][nt][2], v11 = acc[mt][nt][3];

            if (part < 2) {
                const int i = d >> 1;
                float ex   = (float)(2 * i) * (1.0f / 64.0f);
                float freq = powf(10000.0f, -ex);
                float sn0, cs0, sn1, cs1;
                sincosf((float)s0 * freq, &sn0, &cs0);
                sincosf((float)s1 * freq, &sn1, &cs1);
                float a0 = v00 * cs0 - v01 * sn0, b0v = v00 * sn0 + v01 * cs0;
                float a1 = v10 * cs1 - v11 * sn1, b1v = v10 * sn1 + v11 * cs1;

                bf16* dh = part == 0 ? qh : kh;
                bf16* dl = part == 0 ? ql : kl;
                {
                    size_t ro = (((size_t)b0 * N_HEADS + hh) * S_LEN + s0) * 64 + d;
                    bf16 h0 = __float2bfloat16(a0);
                    bf16 l0 = __float2bfloat16(a0 - __bfloat162float(h0));
                    bf16 h1 = __float2bfloat16(b0v);
                    bf16 l1 = __float2bfloat16(b0v - __bfloat162float(h1));
                    *(uint32_t*)(dh + ro) = pack_bf2(h0, h1);
                    *(uint32_t*)(dl + ro) = pack_bf2(l0, l1);
                }
                {
                    size_t ro = (((size_t)b1 * N_HEADS + hh) * S_LEN + s1) * 64 + d;
                    bf16 h0 = __float2bfloat16(a1);
                    bf16 l0 = __float2bfloat16(a1 - __bfloat162float(h0));
                    bf16 h1 = __float2bfloat16(b1v);
                    bf16 l1 = __float2bfloat16(b1v - __bfloat162float(h1));
                    *(uint32_t*)(dh + ro) = pack_bf2(h0, h1);
                    *(uint32_t*)(dl + ro) = pack_bf2(l0, l1);
                }
            } else {
                size_t vo0 = (((size_t)b0 * N_HEADS + hh) * 64 + d) * S_LEN + s0;
                size_t vo1 = (((size_t)b1 * N_HEADS + hh) * 64 + d) * S_LEN + s1;
                bf16 h0 = __float2bfloat16(v00);
                vth[vo0] = h0; vtl[vo0] = __float2bfloat16(v00 - __bfloat162float(h0));
                h0 = __float2bfloat16(v01);
                vth[vo0 + S_LEN] = h0; vtl[vo0 + S_LEN] = __float2bfloat16(v01 - __bfloat162float(h0));
                h0 = __float2bfloat16(v10);
                vth[vo1] = h0; vtl[vo1] = __float2bfloat16(v10 - __bfloat162float(h0));
                h0 = __float2bfloat16(v11);
                vth[vo1 + S_LEN] = h0; vtl[vo1 + S_LEN] = __float2bfloat16(v11 - __bfloat162float(h0));
            }
        }
    }
}

// ---------------- fp32 SGEMM, dual-output (selection path, validated) -----------
__global__ __launch_bounds__(256) void sgemm_nn2(const float* __restrict__ A,
                                                 const float* __restrict__ B1,
                                                 float* __restrict__ C1,
                                                 const float* __restrict__ B2,
                                                 float* __restrict__ C2,
                                                 int M, int N, int K)
{
    const float* B = blockIdx.z ? B2 : B1;
    float*       C = blockIdx.z ? C2 : C1;

    __shared__ float As[2][8][128];
    __shared__ float Bs[2][8][128];

    const int tid = threadIdx.x;
    const int bx = blockIdx.x, by = blockIdx.y;
    const int tx = tid & 15, ty = tid >> 4;

    const int arow = tid >> 1, ak = (tid & 1) * 4;
    const int brow = tid >> 5, bcol = (tid & 31) * 4;

    const float* Ag = A + (size_t)(by * 128 + arow) * K + ak;
    const float* Bg = B + (size_t)brow * N + bx * 128 + bcol;

    float4 af = *(const float4*)Ag;
    float4 bf = *(const float4*)Bg;
    As[0][ak + 0][arow] = af.x;
    As[0][ak + 1][arow] = af.y;
    As[0][ak + 2][arow] = af.z;
    As[0][ak + 3][arow] = af.w;
    *(float4*)&Bs[0][brow][bcol] = bf;
    __syncthreads();

    float acc[8][8];
#pragma unroll
    for (int i = 0; i < 8; i++)
#pragma unroll
        for (int j = 0; j < 8; j++) acc[i][j] = 0.f;

    int buf = 0;
    for (int k0 = 8; k0 <= K; k0 += 8) {
        const bool next = (k0 < K);
        if (next) {
            af = *(const float4*)(Ag + k0);
            bf = *(const float4*)(Bg + (size_t)k0 * N);
        }
#pragma unroll
        for (int kk = 0; kk < 8; kk++) {
            float a[8], b[8];
            *(float4*)&a[0] = *(const float4*)&As[buf][kk][ty * 8];
            *(float4*)&a[4] = *(const float4*)&As[buf][kk][ty * 8 + 4];
            *(float4*)&b[0] = *(const float4*)&Bs[buf][kk][tx * 8];
            *(float4*)&b[4] = *(const float4*)&Bs[buf][kk][tx * 8 + 4];
#pragma unroll
            for (int i = 0; i < 8; i++)
#pragma unroll
                for (int j = 0; j < 8; j++)
                    acc[i][j] += a[i] * b[j];
        }
        if (next) {
            buf ^= 1;
            As[buf][ak + 0][arow] = af.x;
            As[buf][ak + 1][arow] = af.y;
            As[buf][ak + 2][arow] = af.z;
            As[buf][ak + 3][arow] = af.w;
            *(float4*)&Bs[buf][brow][bcol] = bf;
            __syncthreads();
        }
    }

#pragma unroll
    for (int i = 0; i < 8; i++) {
        float* Crow = C + (size_t)(by * 128 + ty * 8 + i) * N + bx * 128 + tx * 8;
        *(float4*)Crow       = make_float4(acc[i][0], acc[i][1], acc[i][2], acc[i][3]);
        *(float4*)(Crow + 4) = make_float4(acc[i][4], acc[i][5], acc[i][6], acc[i][7]);
    }
}

// ---------------- top-k: 8 rows/block, 4-way k-blocked dot, warp radix ----------
// Per-(k,r) accumulation uses the IDENTICAL source expression and i-order as the
// validated kernel (selection-exact). Each iq smem load now feeds 4 k-rows.
__global__ __launch_bounds__(256) void topk8_kernel(const float* __restrict__ iq,
                                                    const float* __restrict__ ik,
                                                    const int* __restrict__ topk_ptr,
                                                    unsigned* __restrict__ mask)
{
    extern __shared__ __align__(16) unsigned dsm[];
    float*    iqs  = (float*)dsm;
    unsigned* keys = dsm + 8 * 256;
    unsigned* hist = keys + 8 * 2048;
    __shared__ unsigned s_prefix[8];
    __shared__ int      s_kr[8];
    __shared__ unsigned s_thr[8];

    const int tid = threadIdx.x;
    const int gid = blockIdx.x;
    const int b = (gid * 8) >> 11;
    const int qbase = (gid * 8) & (S_LEN - 1);
    const int qmax = qbase + 7;

    for (int i = tid; i < 8 * IDX_D; i += 256) {
        int r = i >> 8, c = i & 255;
        iqs[i] = iq[(size_t)(b * S_LEN + qbase + r) * IDX_D + c];
    }
    __syncthreads();

    // scores: each thread handles 4 k-rows per 1024-chunk (k, k+256, k+512, k+768)
    for (int k0 = 0; k0 < S_LEN; k0 += 1024) {
        const int kb = k0 + tid;
        if (k0 <= qmax) {
            const float4* ikr[4];
#pragma unroll
            for (int j = 0; j < 4; j++) {
                int kj = kb + j * 256;
                int kc = kj <= qmax ? kj : qmax;   // clamped (safe) load row
                ikr[j] = (const float4*)(ik + (size_t)(b * S_LEN + kc) * IDX_D);
            }
            float acc[4][8];
#pragma unroll
            for (int j = 0; j < 4; j++)
#pragma unroll
                for (int r = 0; r < 8; r++) acc[j][r] = 0.f;

#pragma unroll 2
            for (int i = 0; i < 64; i++) {
                float4 c0 = ikr[0][i];
                float4 c1 = ikr[1][i];
                float4 c2 = ikr[2][i];
                float4 c3 = ikr[3][i];
#pragma unroll
                for (int r = 0; r < 8; r++) {
                    float4 a = ((const float4*)(iqs + r * 256))[i];
                    acc[0][r] += a.x * c0.x + a.y * c0.y + a.z * c0.z + a.w * c0.w;
                    acc[1][r] += a.x * c1.x + a.y * c1.y + a.z * c1.z + a.w * c1.w;
                    acc[2][r] += a.x * c2.x + a.y * c2.y + a.z * c2.z + a.w * c2.w;
                    acc[3][r] += a.x * c3.x + a.y * c3.y + a.z * c3.z + a.w * c3.w;
                }
            }
#pragma unroll
            for (int j = 0; j < 4; j++) {
                int kj = kb + j * 256;
#pragma unroll
                for (int r = 0; r < 8; r++) {
                    unsigned key = 0u;
                    if (kj <= qbase + r) {
                        unsigned u = __float_as_uint(acc[j][r]);
                        key = (u & 0x80000000u) ? ~u : (u | 0x80000000u);
                    }
                    keys[r * S_LEN + kj] = key;
                }
            }
        } else {
#pragma unroll
            for (int j = 0; j < 4; j++) {
                int kj = kb + j * 256;
#pragma unroll
                for (int r = 0; r < 8; r++) keys[r * S_LEN + kj] = 0u;
            }
        }
    }

    int topk = topk_ptr ? topk_ptr[0] : 512;
    if (topk > S_LEN) topk = S_LEN;

    const int row  = tid >> 5;
    const int lane = tid & 31;
    const bool active = (qbase + row + 1 > topk);
    if (lane == 0) { s_prefix[row] = 0u; s_kr[row] = topk; }
    __syncthreads();

    for (int pass = 0; pass < 4; pass++) {
        const int shift = 24 - pass * 8;
        for (int i = tid; i < 8 * 256; i += 256) hist[i] = 0u;
        __syncthreads();
        if (active) {
            const unsigned pref = s_prefix[row];
            const unsigned* kr = keys + row * S_LEN;
            for (int k = lane; k < S_LEN; k += 32) {
                unsigned key = kr[k];
                bool match = (pass == 0) || ((key >> (shift + 8)) == (pref >> (shift + 8)));
                if (match) atomicAdd(&hist[row * 256 + ((key >> shift) & 255u)], 1u);
            }
        }
        __syncthreads();
        if (active && lane == 0) {
            int kk = s_kr[row];
            unsigned p = s_prefix[row];
            const unsigned* hr = hist + row * 256;
            for (int d = 255; d >= 0; d--) {
                int c = (int)hr[d];
                if (kk <= c) { s_prefix[row] = p | ((unsigned)d << shift); break; }
                kk -= c;
            }
            s_kr[row] = kk;
        }
        __syncthreads();
    }
    if (lane == 0) s_thr[row] = active ? s_prefix[row] : 0u;
    __syncthreads();

    for (int w = tid; w < 8 * 64; w += 256) {
        int r = w >> 6, wi = w & 63;
        int q = qbase + r;
        unsigned thr = s_thr[r];
        const unsigned* kr = keys + r * S_LEN;
        unsigned word = 0u;
        int kb2 = wi * 32;
#pragma unroll
        for (int bit = 0; bit < 32; bit++) {
            int k = kb2 + bit;
            unsigned key = kr[k];
            if (k <= q && key >= thr && key != 0u) word |= (1u << bit);
        }
        mask[(size_t)(b * S_LEN + q) * 64 + wi] = word;
    }
}

// ---------------- FA2-style tensor-core masked flash (validated) ----------------
#define KSTR   72
#define KSTRB  144
#define KTILE  (64 * KSTR)
#define FSMEM3 (8 * KTILE * 2)    // 73728 bytes

__global__ __launch_bounds__(256) void flash_mma3(
    const bf16* __restrict__ qh, const bf16* __restrict__ ql,
    const bf16* __restrict__ kh, const bf16* __restrict__ kl,
    const bf16* __restrict__ vth, const bf16* __restrict__ vtl,
    const unsigned* __restrict__ mask, bf16* __restrict__ attn3)
{
    extern __shared__ __align__(16) bf16 sm[];
    const int tid  = threadIdx.x;
    const int warp = tid >> 5, lane = tid & 31;
    const int qt = gridDim.x - 1 - blockIdx.x;
    const int hd = blockIdx.y, b = blockIdx.z;

    const uint32_t sbase = (uint32_t)__cvta_generic_to_shared(sm);

    const size_t bh = (size_t)b * N_HEADS + hd;
    const bf16* qhg  = qh  + (bh * S_LEN + (size_t)qt * 128) * 64;
    const bf16* qlg  = ql  + (bh * S_LEN + (size_t)qt * 128) * 64;
    const bf16* khg  = kh  + bh * S_LEN * 64;
    const bf16* klg  = kl  + bh * S_LEN * 64;
    const bf16* vthg = vth + bh * 64 * (size_t)S_LEN;
    const bf16* vtlg = vtl + bh * 64 * (size_t)S_LEN;

    const uint32_t QHS = sbase + (4 * KTILE) * 2;
    const uint32_t QLS = sbase + (6 * KTILE) * 2;
    for (int c = tid; c < 2048; c += 256) {
        if (c < 1024) {
            int row = c >> 3, ch = c & 7;
            CP16(QHS + row * KSTRB + ch * 16, qhg + (size_t)row * 64 + ch * 8);
        } else {
            int cc = c - 1024;
            int row = cc >> 3, ch = cc & 7;
            CP16(QLS + row * KSTRB + ch * 16, qlg + (size_t)row * 64 + ch * 8);
        }
    }
    CPCOMMIT();

    for (int c = tid; c < 2048; c += 256) {
        int q4 = c >> 9, idx = c & 511;
        int row = idx >> 3, ch = idx & 7;
        uint32_t dst = sbase + (uint32_t)q4 * (KTILE * 2) + row * KSTRB + ch * 16;
        const bf16* src;
        if      (q4 == 0) src = khg  + (size_t)row * 64 + ch * 8;
        else if (q4 == 1) src = klg  + (size_t)row * 64 + ch * 8;
        else if (q4 == 2) src = vthg + (size_t)row * S_LEN + ch * 8;
        else              src = vtlg + (size_t)row * S_LEN + ch * 8;
        CP16(dst, src);
    }
    CPCOMMIT();
    CPWAIT0();
    __syncthreads();

    uint32_t aQh[4][4], aQl[4][4];
    const uint32_t qro = (uint32_t)((warp * 16 + (lane & 15)) * KSTRB + ((lane >> 4) << 3) * 2);
#pragma unroll
    for (int ks = 0; ks < 4; ks++) {
        ldsm_x4(aQh[ks], QHS + qro + ks * 32);
        ldsm_x4(aQl[ks], QLS + qro + ks * 32);
    }
    __syncthreads();

    float O[8][4];
#pragma unroll
    for (int i = 0; i < 8; i++)
#pragma unroll
        for (int j = 0; j < 4; j++) O[i][j] = 0.f;
    float m0 = -1e30f, m1 = -1e30f, l0 = 0.f, l1 = 0.f;

    const int r0 = warp * 16 + (lane >> 2);
    const int q0 = qt * 128 + r0, q1 = q0 + 8;
    const unsigned* mrow0 = mask + ((size_t)b * S_LEN + q0) * 64;
    const unsigned* mrow1 = mask + ((size_t)b * S_LEN + q1) * 64;

    const int browo = (lane & 7) + ((lane >> 4) << 3);
    const uint32_t bcol = (uint32_t)((((lane >> 3) & 1) << 3) * 2);

    const int ktmax = 2 * qt + 1;

    for (int kt = 0; kt <= ktmax; kt++) {
        const int buf = kt & 1;
        if (kt < ktmax) {
            const uint32_t dbase = sbase + (uint32_t)(buf ^ 1) * (4 * KTILE * 2);
            const size_t kro = (size_t)(kt + 1) * 64;
            for (int c = tid; c < 2048; c += 256) {
                int q4 = c >> 9, idx = c & 511;
                int row = idx >> 3, ch = idx & 7;
                uint32_t dst = dbase + (uint32_t)q4 * (KTILE * 2) + row * KSTRB + ch * 16;
                const bf16* src;
                if      (q4 == 0) src = khg  + (kro + row) * 64 + ch * 8;
                else if (q4 == 1) src = klg  + (kro + row) * 64 + ch * 8;
                else if (q4 == 2) src = vthg + (size_t)row * S_LEN + kro + ch * 8;
                else              src = vtlg + (size_t)row * S_LEN + kro + ch * 8;
                CP16(dst, src);
            }
            CPCOMMIT();
            CPWAIT1();
        } else {
            CPWAIT0();
        }
        __syncthreads();

        const uint32_t tb  = sbase + (uint32_t)buf * (4 * KTILE * 2);
        const uint32_t sKh = tb;
        const uint32_t sKl = tb + KTILE * 2;
        const uint32_t sVh = tb + 2 * KTILE * 2;
        const uint32_t sVl = tb + 3 * KTILE * 2;

        float S_[8][4];
#pragma unroll
        for (int i = 0; i < 8; i++)
#pragma unroll
            for (int j = 0; j < 4; j++) S_[i][j] = 0.f;

#pragma unroll
        for (int ks = 0; ks < 4; ks++) {
#pragma unroll
            for (int nt2 = 0; nt2 < 4; nt2++) {
                const uint32_t ro = (uint32_t)((nt2 * 16 + browo) * KSTRB) + bcol + ks * 32;
                uint32_t bb[4];
                ldsm_x4(bb, sKh + ro);
                mma16816(S_[nt2 * 2],     aQh[ks], bb);
                mma16816(S_[nt2 * 2 + 1], aQh[ks], bb + 2);
                mma16816(S_[nt2 * 2],     aQl[ks], bb);
                mma16816(S_[nt2 * 2 + 1], aQl[ks], bb + 2);
                ldsm_x4(bb, sKl + ro);
                mma16816(S_[nt2 * 2],     aQh[ks], bb);
                mma16816(S_[nt2 * 2 + 1], aQh[ks], bb + 2);
            }
        }

        const unsigned mw00 = mrow0[kt * 2], mw01 = mrow0[kt * 2 + 1];
        const unsigned mw10 = mrow1[kt * 2], mw11 = mrow1[kt * 2 + 1];
        float mx0 = -1e30f, mx1 = -1e30f;
#pragma unroll
        for (int nf = 0; nf < 8; nf++) {
            int c = nf * 8 + 2 * (lane & 3);
#pragma unroll
            for (int e = 0; e < 2; e++) {
                int cc = c + e;
                unsigned w0 = (cc < 32 ? mw00 : mw01) >> (cc & 31);
                unsigned w1 = (cc < 32 ? mw10 : mw11) >> (cc & 31);
                float v0 = (w0 & 1u) ? S_[nf][e] * 0.125f     : -1e30f;
                float v1 = (w1 & 1u) ? S_[nf][e + 2] * 0.125f : -1e30f;
                S_[nf][e] = v0; S_[nf][e + 2] = v1;
                mx0 = fmaxf(mx0, v0); mx1 = fmaxf(mx1, v1);
            }
        }
        mx0 = fmaxf(mx0, __shfl_xor_sync(0xffffffffu, mx0, 1));
        mx0 = fmaxf(mx0, __shfl_xor_sync(0xffffffffu, mx0, 2));
        mx1 = fmaxf(mx1, __shfl_xor_sync(0xffffffffu, mx1, 1));
        mx1 = fmaxf(mx1, __shfl_xor_sync(0xffffffffu, mx1, 2));
        float mn0 = fmaxf(m0, mx0), mn1 = fmaxf(m1, mx1);
        float c0 = __expf(m0 - mn0), c1 = __expf(m1 - mn1);
        float ls0 = 0.f, ls1 = 0.f;
#pragma unroll
        for (int nf = 0; nf < 8; nf++) {
#pragma unroll
            for (int e = 0; e < 2; e++) {
                float p0 = (S_[nf][e]     > -1e29f) ? __expf(S_[nf][e]     - mn0) : 0.f;
                float p1 = (S_[nf][e + 2] > -1e29f) ? __expf(S_[nf][e + 2] - mn1) : 0.f;
                S_[nf][e] = p0; S_[nf][e + 2] = p1;
                ls0 += p0; ls1 += p1;
            }
        }
        ls0 += __shfl_xor_sync(0xffffffffu, ls0, 1);
        ls0 += __shfl_xor_sync(0xffffffffu, ls0, 2);
        ls1 += __shfl_xor_sync(0xffffffffu, ls1, 1);
        ls1 += __shfl_xor_sync(0xffffffffu, ls1, 2);
        l0 = l0 * c0 + ls0; l1 = l1 * c1 + ls1;
        m0 = mn0; m1 = mn1;
#pragma unroll
        for (int nf = 0; nf < 8; nf++) {
            O[nf][0] *= c0; O[nf][1] *= c0;
            O[nf][2] *= c1; O[nf][3] *= c1;
        }

        uint32_t aPh[4][4], aPl[4][4];
#pragma unroll
        for (int ks = 0; ks < 4; ks++) {
#pragma unroll
            for (int half = 0; half < 2; half++) {
                const float* Sf = S_[2 * ks + half];
                bf16 h0 = __float2bfloat16(Sf[0]);
                bf16 l0b = __float2bfloat16(Sf[0] - __bfloat162float(h0));
                bf16 h1 = __float2bfloat16(Sf[1]);
                bf16 l1b = __float2bfloat16(Sf[1] - __bfloat162float(h1));
                bf16 h2 = __float2bfloat16(Sf[2]);
                bf16 l2b = __float2bfloat16(Sf[2] - __bfloat162float(h2));
                bf16 h3 = __float2bfloat16(Sf[3]);
                bf16 l3b = __float2bfloat16(Sf[3] - __bfloat162float(h3));
                aPh[ks][half * 2]     = pack_bf2(h0, h1);
                aPh[ks][half * 2 + 1] = pack_bf2(h2, h3);
                aPl[ks][half * 2]     = pack_bf2(l0b, l1b);
                aPl[ks][half * 2 + 1] = pack_bf2(l2b, l3b);
            }
        }

#pragma unroll
        for (int ks = 0; ks < 4; ks++) {
#pragma unroll
            for (int nt2 = 0; nt2 < 4; nt2++) {
                const uint32_t ro = (uint32_t)((nt2 * 16 + browo) * KSTRB) + bcol + ks * 32;
                uint32_t bb[4];
                ldsm_x4(bb, sVh + ro);
                mma16816(O[nt2 * 2],     aPh[ks], bb);
                mma16816(O[nt2 * 2 + 1], aPh[ks], bb + 2);
                mma16816(O[nt2 * 2],     aPl[ks], bb);
                mma16816(O[nt2 * 2 + 1], aPl[ks], bb + 2);
                ldsm_x4(bb, sVl + ro);
                mma16816(O[nt2 * 2],     aPh[ks], bb);
                mma16816(O[nt2 * 2 + 1], aPh[ks], bb + 2);
            }
        }
        __syncthreads();
    }

    float inv0 = 1.0f / l0, inv1 = 1.0f / l1;
    bf16* o3r0 = attn3 + ((size_t)b * S_LEN + q0) * 3072;
    bf16* o3r1 = attn3 + ((size_t)b * S_LEN + q1) * 3072;
#pragma unroll
    for (int nf = 0; nf < 8; nf++) {
        int c = nf * 8 + 2 * (lane & 3);
        {
            float v0 = O[nf][0] * inv0, v1 = O[nf][1] * inv0;
            bf16 h0 = __float2bfloat16(v0);
            bf16 l0b = __float2bfloat16(v0 - __bfloat162float(h0));
            bf16 h1 = __float2bfloat16(v1);
            bf16 l1b = __float2bfloat16(v1 - __bfloat162float(h1));
            uint32_t* p = (uint32_t*)(o3r0 + 3 * (size_t)(hd * 64 + c));
            p[0] = pack_bf2(h0, l0b);
            p[1] = pack_bf2(h0, h1);
            p[2] = pack_bf2(l1b, h1);
        }
        {
            float v0 = O[nf][2] * inv1, v1 = O[nf][3] * inv1;
            bf16 h0 = __float2bfloat16(v0);
            bf16 l0b = __float2bfloat16(v0 - __bfloat162float(h0));
            bf16 h1 = __float2bfloat16(v1);
            bf16 l1b = __float2bfloat16(v1 - __bfloat162float(h1));
            uint32_t* p = (uint32_t*)(o3r1 + 3 * (size_t)(hd * 64 + c));
            p[0] = pack_bf2(h0, l0b);
            p[1] = pack_bf2(h0, h1);
            p[2] = pack_bf2(l1b, h1);
        }
    }
}

// ---------------- launcher with fork/join stream overlap -------------------------
extern "C" void kernel_launch(void* const* d_in, const int* in_sizes, int n_in,
                              void* d_out, int out_size)
{
    static cudaStream_t s_sel = nullptr;
    static cudaEvent_t  ev_fork = nullptr, ev_join = nullptr, ev_w = nullptr;
    if (!s_sel) {
        cudaStreamCreateWithFlags(&s_sel, cudaStreamNonBlocking);
        cudaEventCreateWithFlags(&ev_fork, cudaEventDisableTiming);
        cudaEventCreateWithFlags(&ev_join, cudaEventDisableTiming);
        cudaEventCreateWithFlags(&ev_w, cudaEventDisableTiming);
    }

    const float* x    = nullptr;
    const float* Wqkv = nullptr;
    const float* Wo   = nullptr;
    const float* Wiq  = nullptr;
    const float* Wik  = nullptr;
    const int*   topk = nullptr;
    for (int i = 0; i < n_in; i++) {
        int sz = in_sizes[i];
        if      (sz == D_MODEL * 3 * D_MODEL)       Wqkv = (const float*)d_in[i];
        else if (sz == D_MODEL * D_MODEL)           Wo   = (const float*)d_in[i];
        else if (sz == D_MODEL * IDX_D) { if (!Wiq) Wiq  = (const float*)d_in[i];
                                          else      Wik  = (const float*)d_in[i]; }
        else if (sz <= 4)                           topk = (const int*)d_in[i];
        else                                        x    = (const float*)d_in[i];
    }

    const int BS = out_size / D_MODEL;
    const int Bn = BS / S_LEN;

    float *iq, *ik; unsigned* mask;
    bf16 *x3, *attn3, *wqkv3, *wo3, *qh, *ql, *kh, *kl, *vth, *vtl;
    cudaGetSymbolAddress((void**)&iq,    g_iq);
    cudaGetSymbolAddress((void**)&ik,    g_ik);
    cudaGetSymbolAddress((void**)&mask,  g_mask);
    cudaGetSymbolAddress((void**)&x3,    g_x3);
    cudaGetSymbolAddress((void**)&attn3, g_attn3);
    cudaGetSymbolAddress((void**)&wqkv3, g_wqkv3);
    cudaGetSymbolAddress((void**)&wo3,   g_wo3);
    cudaGetSymbolAddress((void**)&qh,    g_qh);
    cudaGetSymbolAddress((void**)&ql,    g_ql);
    cudaGetSymbolAddress((void**)&kh,    g_kh);
    cudaGetSymbolAddress((void**)&kl,    g_kl);
    cudaGetSymbolAddress((void**)&vth,   g_vth);
    cudaGetSymbolAddress((void**)&vtl,   g_vtl);

    const int K3 = 3 * D_MODEL;
    const int TOPK_SMEM = (8 * 256 + 8 * 2048 + 8 * 256) * 4;

    cudaFuncSetAttribute(mma_gemm, cudaFuncAttributeMaxDynamicSharedMemorySize, GEMM_SMEM);
    cudaFuncSetAttribute(mma_gemm_qkv, cudaFuncAttributeMaxDynamicSharedMemorySize, GEMM_SMEM);
    cudaFuncSetAttribute(topk8_kernel, cudaFuncAttributeMaxDynamicSharedMemorySize, TOPK_SMEM);
    cudaFuncSetAttribute(flash_mma3, cudaFuncAttributeMaxDynamicSharedMemorySize, FSMEM3);

    // ---- fork: weight splits + selection chain on s_sel ----
    cudaEventRecord(ev_fork, 0);
    cudaStreamWaitEvent(s_sel, ev_fork, 0);
    {
        dim3 blk(32, 8);
        split_bT<<<dim3(3 * D_MODEL / 32, D_MODEL / 32), blk, 0, s_sel>>>(Wqkv, wqkv3, D_MODEL, 3 * D_MODEL);
        cudaEventRecord(ev_w, s_sel);
        split_bT<<<dim3(D_MODEL / 32, D_MODEL / 32), blk, 0, s_sel>>>(Wo, wo3, D_MODEL, D_MODEL);
    }
    sgemm_nn2<<<dim3(IDX_D / 128, BS / 128, 2), 256, 0, s_sel>>>(
        x, Wiq, iq, Wik, ik, BS, IDX_D, D_MODEL);
    topk8_kernel<<<BS / 8, 256, TOPK_SMEM, s_sel>>>(iq, ik, topk, mask);
    cudaEventRecord(ev_join, s_sel);

    // ---- smooth chain on the main (capture) stream ----
    split_a<<<(BS * D_MODEL + 255) / 256, 256>>>(x, x3, BS * D_MODEL);
    cudaStreamWaitEvent(0, ev_w, 0);
    mma_gemm_qkv<<<dim3(3 * D_MODEL / BNg, BS / BMg), 256, GEMM_SMEM>>>(
        x3, wqkv3, qh, ql, kh, kl, vth, vtl, K3);

    // ---- join: flash needs the mask ----
    cudaStreamWaitEvent(0, ev_join, 0);
    flash_mma3<<<dim3(S_LEN / 128, N_HEADS, Bn), 256, FSMEM3>>>(
        qh, ql, kh, kl, vth, vtl, mask, attn3);

    // output projection (reads attn3 written by flash epilogue)
    mma_gemm<<<dim3(D_MODEL / BNg, BS / BMg), 256, GEMM_SMEM>>>(
        attn3, wo3, (float*)d_out, BS, D_MODEL, K3);
}

// round 17
// speedup vs baseline: 1.0959x; 1.0015x over previous
#include <cuda_runtime.h>
#include <cuda_bf16.h>
#include <cstdint>
#include <math.h>

#define S_LEN   2048
#define D_MODEL 1024
#define N_HEADS 16
#define IDX_D   256
#define MAXB    2
#define BS_MAX  (MAXB * S_LEN)

typedef __nv_bfloat16 bf16;

// ---------------- scratch (static device globals; no allocation) ----------------
__device__ float    g_iq  [(size_t)BS_MAX * IDX_D];
__device__ float    g_ik  [(size_t)BS_MAX * IDX_D];
__device__ unsigned g_mask[(size_t)BS_MAX * (S_LEN / 32)];

__device__ __align__(16) bf16 g_x3   [(size_t)BS_MAX * 3 * D_MODEL];
__device__ __align__(16) bf16 g_attn3[(size_t)BS_MAX * 3 * D_MODEL];
__device__ __align__(16) bf16 g_wqkv3[(size_t)(3 * D_MODEL) * 3 * D_MODEL];
__device__ __align__(16) bf16 g_wo3  [(size_t)D_MODEL * 3 * D_MODEL];

// flash operands: h/l split pairs
__device__ __align__(16) bf16 g_qh [(size_t)MAXB * N_HEADS * S_LEN * 64];
__device__ __align__(16) bf16 g_ql [(size_t)MAXB * N_HEADS * S_LEN * 64];
__device__ __align__(16) bf16 g_kh [(size_t)MAXB * N_HEADS * S_LEN * 64];
__device__ __align__(16) bf16 g_kl [(size_t)MAXB * N_HEADS * S_LEN * 64];
__device__ __align__(16) bf16 g_vth[(size_t)MAXB * N_HEADS * 64 * S_LEN];
__device__ __align__(16) bf16 g_vtl[(size_t)MAXB * N_HEADS * 64 * S_LEN];

// ---------------- bf16x3 split conversions --------------------------------------
__global__ void split_a(const float* __restrict__ s, bf16* __restrict__ d, int n)
{
    int i = blockIdx.x * blockDim.x + threadIdx.x;
    if (i >= n) return;
    float v = s[i];
    bf16 h = __float2bfloat16(v);
    bf16 l = __float2bfloat16(v - __bfloat162float(h));
    d[3 * i] = h; d[3 * i + 1] = l; d[3 * i + 2] = h;
}

__global__ void split_bT(const float* __restrict__ W, bf16* __restrict__ out,
                         int K, int N)
{
    __shared__ float t[32][33];
    int n0 = blockIdx.x * 32, k0 = blockIdx.y * 32;
    int tx = threadIdx.x, ty = threadIdx.y;   // block (32,8)
    for (int i = ty; i < 32; i += 8)
        t[i][tx] = W[(size_t)(k0 + i) * N + n0 + tx];
    __syncthreads();
    for (int r = ty; r < 32; r += 8) {
        float v = t[tx][r];
        bf16 h = __float2bfloat16(v);
        bf16 l = __float2bfloat16(v - __bfloat162float(h));
        size_t o = (size_t)(n0 + r) * (3 * K) + 3 * (size_t)(k0 + tx);
        out[o] = h; out[o + 1] = h; out[o + 2] = l;
    }
}

// ---------------- shared mma helpers ---------------------------------------------
#define BMg 128
#define BNg 128
#define BKg 32
#define GEMM_SMEM (3 * (BMg + BNg) * 40 * 2)   // 61440 bytes

__device__ __forceinline__ void ldsm_x4(uint32_t* r, uint32_t a) {
    asm volatile("ldmatrix.sync.aligned.m8n8.x4.shared.b16 {%0,%1,%2,%3}, [%4];"
                 : "=r"(r[0]), "=r"(r[1]), "=r"(r[2]), "=r"(r[3]) : "r"(a));
}
__device__ __forceinline__ void mma16816(float* c, const uint32_t* a, const uint32_t* b) {
    asm volatile("mma.sync.aligned.m16n8k16.row.col.f32.bf16.bf16.f32 "
                 "{%0,%1,%2,%3},{%4,%5,%6,%7},{%8,%9},{%0,%1,%2,%3};"
                 : "+f"(c[0]), "+f"(c[1]), "+f"(c[2]), "+f"(c[3])
                 : "r"(a[0]), "r"(a[1]), "r"(a[2]), "r"(a[3]), "r"(b[0]), "r"(b[1]));
}
#define CP16(sa, ga) asm volatile("cp.async.cg.shared.global [%0], [%1], 16;\n" :: "r"(sa), "l"(ga))
#define CPCOMMIT()   asm volatile("cp.async.commit_group;\n" ::: "memory")
#define CPWAIT0()    asm volatile("cp.async.wait_group 0;\n" ::: "memory")
#define CPWAIT1()    asm volatile("cp.async.wait_group 1;\n" ::: "memory")

__device__ __forceinline__ uint32_t pack_bf2(bf16 a, bf16 b) {
    return (uint32_t)__bfloat16_as_ushort(a) |
           ((uint32_t)__bfloat16_as_ushort(b) << 16);
}

// ---------------- GEMM mainloop body (macro keeps both kernels identical) -------
#define GEMM_BODY(A_, B_, K_)                                                      \
    const uint32_t BUFA  = BMg * 40 * 2;                                           \
    const uint32_t BUFAB = (BMg + BNg) * 40 * 2;                                   \
    const uint32_t sbase = (uint32_t)__cvta_generic_to_shared(gsm);                \
    const uint32_t sA = sbase;                                                     \
    const uint32_t sB = sbase + BUFA;                                              \
    const int ldrow = tid >> 2;                                                    \
    const int ldch  = (tid & 3) * 8;                                               \
    float acc[4][4][4];                                                            \
    _Pragma("unroll")                                                              \
    for (int i = 0; i < 4; i++)                                                    \
        _Pragma("unroll")                                                          \
        for (int j = 0; j < 4; j++)                                                \
            _Pragma("unroll")                                                      \
            for (int t = 0; t < 4; t++) acc[i][j][t] = 0.f;                        \
    const int KT = (K_) / BKg;                                                     \
    _Pragma("unroll")                                                              \
    for (int pf = 0; pf < 2; pf++) {                                               \
        int k0 = pf * BKg;                                                         \
        _Pragma("unroll")                                                          \
        for (int hh = 0; hh < 2; hh++) {                                           \
            int row = ldrow + hh * 64;                                             \
            CP16(sA + pf * BUFAB + (uint32_t)(row * 40 + ldch) * 2,                \
                 (A_) + (size_t)(by * BMg + row) * (K_) + k0 + ldch);              \
            CP16(sB + pf * BUFAB + (uint32_t)(row * 40 + ldch) * 2,                \
                 (B_) + (size_t)(bx * BNg + row) * (K_) + k0 + ldch);              \
        }                                                                          \
        CPCOMMIT();                                                                \
    }                                                                              \
    CPWAIT1();                                                                     \
    __syncthreads();                                                               \
    const int browo = (lane & 7) + ((lane >> 4) << 3);                             \
    const int bkoff = (((lane >> 3) & 1) << 3);                                    \
    for (int kt = 0; kt < KT; kt++) {                                              \
        const uint32_t bo = (uint32_t)(kt % 3) * BUFAB;                            \
        _Pragma("unroll")                                                          \
        for (int ks = 0; ks < BKg; ks += 16) {                                     \
            uint32_t af[4][4], bfr[2][4];                                          \
            const int arow = wm * 64 + (lane & 15);                                \
            const int acol = ks + ((lane >> 4) << 3);                              \
            _Pragma("unroll")                                                      \
            for (int mt = 0; mt < 4; mt++)                                         \
                ldsm_x4(af[mt], sA + bo +                                          \
                        (uint32_t)((arow + mt * 16) * 40 + acol) * 2);             \
            _Pragma("unroll")                                                      \
            for (int nt2 = 0; nt2 < 2; nt2++)                                      \
                ldsm_x4(bfr[nt2], sB + bo +                                        \
                        (uint32_t)((wn * 32 + nt2 * 16 + browo) * 40 + ks + bkoff) * 2); \
            _Pragma("unroll")                                                      \
            for (int mt = 0; mt < 4; mt++)                                         \
                _Pragma("unroll")                                                  \
                for (int nt = 0; nt < 4; nt++)                                     \
                    mma16816(acc[mt][nt], af[mt], bfr[nt >> 1] + (nt & 1) * 2);    \
        }                                                                          \
        __syncthreads();                                                           \
        if (kt + 2 < KT) {                                                         \
            const uint32_t po = (uint32_t)((kt + 2) % 3) * BUFAB;                  \
            const int k0 = (kt + 2) * BKg;                                         \
            _Pragma("unroll")                                                      \
            for (int hh = 0; hh < 2; hh++) {                                       \
                int row = ldrow + hh * 64;                                         \
                CP16(sA + po + (uint32_t)(row * 40 + ldch) * 2,                    \
                     (A_) + (size_t)(by * BMg + row) * (K_) + k0 + ldch);          \
                CP16(sB + po + (uint32_t)(row * 40 + ldch) * 2,                    \
                     (B_) + (size_t)(bx * BNg + row) * (K_) + k0 + ldch);          \
            }                                                                      \
            CPCOMMIT();                                                            \
        }                                                                          \
        if (kt + 1 < KT) {                                                         \
            if (kt + 2 < KT) CPWAIT1(); else CPWAIT0();                            \
            __syncthreads();                                                       \
        }                                                                          \
    }

// ---------------- plain NT GEMM (Wo projection; validated) ----------------------
__global__ __launch_bounds__(256) void mma_gemm(
    const bf16* __restrict__ A, const bf16* __restrict__ B, float* __restrict__ C,
    int M, int N, int K)
{
    extern __shared__ __align__(16) bf16 gsm[];
    const int bx = blockIdx.x, by = blockIdx.y;
    const int tid  = threadIdx.x;
    const int warp = tid >> 5, lane = tid & 31;
    const int wm = warp & 1, wn = warp >> 1;

    GEMM_BODY(A, B, K)

#pragma unroll
    for (int mt = 0; mt < 4; mt++) {
#pragma unroll
        for (int nt = 0; nt < 4; nt++) {
            int row = by * BMg + wm * 64 + mt * 16 + (lane >> 2);
            int col = bx * BNg + wn * 32 + nt * 8 + (lane & 3) * 2;
            float2 v0 = make_float2(acc[mt][nt][0], acc[mt][nt][1]);
            float2 v1 = make_float2(acc[mt][nt][2], acc[mt][nt][3]);
            *(float2*)&C[(size_t)row * N + col]       = v0;
            *(float2*)&C[(size_t)(row + 8) * N + col] = v1;
        }
    }
}

// ---------------- QKV GEMM with fused rope + h/l-split epilogue (validated) -----
__global__ __launch_bounds__(256) void mma_gemm_qkv(
    const bf16* __restrict__ A, const bf16* __restrict__ B,
    bf16* __restrict__ qh, bf16* __restrict__ ql,
    bf16* __restrict__ kh, bf16* __restrict__ kl,
    bf16* __restrict__ vth, bf16* __restrict__ vtl,
    int K)
{
    extern __shared__ __align__(16) bf16 gsm[];
    const int bx = blockIdx.x, by = blockIdx.y;
    const int tid  = threadIdx.x;
    const int warp = tid >> 5, lane = tid & 31;
    const int wm = warp & 1, wn = warp >> 1;

    GEMM_BODY(A, B, K)

    const int part = bx >> 3;                         // 0=Q, 1=K, 2=V
#pragma unroll
    for (int mt = 0; mt < 4; mt++) {
        const int tok0 = by * BMg + wm * 64 + mt * 16 + (lane >> 2);
        const int tok1 = tok0 + 8;
        const int b0 = tok0 >> 11, s0 = tok0 & (S_LEN - 1);
        const int b1 = tok1 >> 11, s1 = tok1 & (S_LEN - 1);
#pragma unroll
        for (int nt = 0; nt < 4; nt++) {
            const int col = bx * BNg + wn * 32 + nt * 8 + (lane & 3) * 2;
            const int pc = col & (D_MODEL - 1);
            const int hh = pc >> 6;
            const int d  = pc & 63;
            float v00 = acc[mt][nt][0], v01 = acc[mt][nt][1];
            float v10 = acc[mt][nt][2], v11 = acc[mt][nt][3];

            if (part < 2) {
                const int i = d >> 1;
                float ex   = (float)(2 * i) * (1.0f / 64.0f);
                float freq = powf(10000.0f, -ex);
                float sn0, cs0, sn1, cs1;
                sincosf((float)s0 * freq, &sn0, &cs0);
                sincosf((float)s1 * freq, &sn1, &cs1);
                float a0 = v00 * cs0 - v01 * sn0, b0v = v00 * sn0 + v01 * cs0;
                float a1 = v10 * cs1 - v11 * sn1, b1v = v10 * sn1 + v11 * cs1;

                bf16* dh = part == 0 ? qh : kh;
                bf16* dl = part == 0 ? ql : kl;
                {
                    size_t ro = (((size_t)b0 * N_HEADS + hh) * S_LEN + s0) * 64 + d;
                    bf16 h0 = __float2bfloat16(a0);
                    bf16 l0 = __float2bfloat16(a0 - __bfloat162float(h0));
                    bf16 h1 = __float2bfloat16(b0v);
                    bf16 l1 = __float2bfloat16(b0v - __bfloat162float(h1));
                    *(uint32_t*)(dh + ro) = pack_bf2(h0, h1);
                    *(uint32_t*)(dl + ro) = pack_bf2(l0, l1);
                }
                {
                    size_t ro = (((size_t)b1 * N_HEADS + hh) * S_LEN + s1) * 64 + d;
                    bf16 h0 = __float2bfloat16(a1);
                    bf16 l0 = __float2bfloat16(a1 - __bfloat162float(h0));
                    bf16 h1 = __float2bfloat16(b1v);
                    bf16 l1 = __float2bfloat16(b1v - __bfloat162float(h1));
                    *(uint32_t*)(dh + ro) = pack_bf2(h0, h1);
                    *(uint32_t*)(dl + ro) = pack_bf2(l0, l1);
                }
            } else {
                size_t vo0 = (((size_t)b0 * N_HEADS + hh) * 64 + d) * S_LEN + s0;
                size_t vo1 = (((size_t)b1 * N_HEADS + hh) * 64 + d) * S_LEN + s1;
                bf16 h0 = __float2bfloat16(v00);
                vth[vo0] = h0; vtl[vo0] = __float2bfloat16(v00 - __bfloat162float(h0));
                h0 = __float2bfloat16(v01);
                vth[vo0 + S_LEN] = h0; vtl[vo0 + S_LEN] = __float2bfloat16(v01 - __bfloat162float(h0));
                h0 = __float2bfloat16(v10);
                vth[vo1] = h0; vtl[vo1] = __float2bfloat16(v10 - __bfloat162float(h0));
                h0 = __float2bfloat16(v11);
                vth[vo1 + S_LEN] = h0; vtl[vo1 + S_LEN] = __float2bfloat16(v11 - __bfloat162float(h0));
            }
        }
    }
}

// ---------------- fp32 SGEMM 64x64, dual-output (selection path) ----------------
// Per-output-element accumulation is pure ascending-k scalar FMA -> bit-identical
// to the validated 128x128 version; tiles shrunk for occupancy (512 blocks).
__global__ __launch_bounds__(256) void sgemm_nn2(const float* __restrict__ A,
                                                 const float* __restrict__ B1,
                                                 float* __restrict__ C1,
                                                 const float* __restrict__ B2,
                                                 float* __restrict__ C2,
                                                 int M, int N, int K)
{
    const float* B = blockIdx.z ? B2 : B1;
    float*       C = blockIdx.z ? C2 : C1;

    __shared__ float As[2][16][64];   // k-major
    __shared__ float Bs[2][16][64];

    const int tid = threadIdx.x;
    const int bx = blockIdx.x, by = blockIdx.y;
    const int tx = tid & 15, ty = tid >> 4;

    const int arow = tid >> 2, ak = (tid & 3) * 4;    // A: 64 rows x 16 k
    const int brow = tid >> 4, bcol = (tid & 15) * 4; // B: 16 rows x 64 n

    const float* Ag = A + (size_t)(by * 64 + arow) * K + ak;
    const float* Bg = B + (size_t)brow * N + bx * 64 + bcol;

    float4 af = *(const float4*)Ag;
    float4 bf = *(const float4*)Bg;
    As[0][ak + 0][arow] = af.x;
    As[0][ak + 1][arow] = af.y;
    As[0][ak + 2][arow] = af.z;
    As[0][ak + 3][arow] = af.w;
    *(float4*)&Bs[0][brow][bcol] = bf;
    __syncthreads();

    float acc[4][4];
#pragma unroll
    for (int i = 0; i < 4; i++)
#pragma unroll
        for (int j = 0; j < 4; j++) acc[i][j] = 0.f;

    int buf = 0;
    for (int k0 = 16; k0 <= K; k0 += 16) {
        const bool next = (k0 < K);
        if (next) {
            af = *(const float4*)(Ag + k0);
            bf = *(const float4*)(Bg + (size_t)k0 * N);
        }
#pragma unroll
        for (int kk = 0; kk < 16; kk++) {
            float a[4], b[4];
            *(float4*)&a[0] = *(const float4*)&As[buf][kk][ty * 4];
            *(float4*)&b[0] = *(const float4*)&Bs[buf][kk][tx * 4];
#pragma unroll
            for (int i = 0; i < 4; i++)
#pragma unroll
                for (int j = 0; j < 4; j++)
                    acc[i][j] += a[i] * b[j];
        }
        if (next) {
            buf ^= 1;
            As[buf][ak + 0][arow] = af.x;
            As[buf][ak + 1][arow] = af.y;
            As[buf][ak + 2][arow] = af.z;
            As[buf][ak + 3][arow] = af.w;
            *(float4*)&Bs[buf][brow][bcol] = bf;
            __syncthreads();
        }
    }

#pragma unroll
    for (int i = 0; i < 4; i++) {
        float* Crow = C + (size_t)(by * 64 + ty * 4 + i) * N + bx * 64 + tx * 4;
        *(float4*)Crow = make_float4(acc[i][0], acc[i][1], acc[i][2], acc[i][3]);
    }
}

// ---------------- top-k: 8 rows/block, 4-way k-blocked dot, warp radix ----------
__global__ __launch_bounds__(256) void topk8_kernel(const float* __restrict__ iq,
                                                    const float* __restrict__ ik,
                                                    const int* __restrict__ topk_ptr,
                                                    unsigned* __restrict__ mask)
{
    extern __shared__ __align__(16) unsigned dsm[];
    float*    iqs  = (float*)dsm;
    unsigned* keys = dsm + 8 * 256;
    unsigned* hist = keys + 8 * 2048;
    __shared__ unsigned s_prefix[8];
    __shared__ int      s_kr[8];
    __shared__ unsigned s_thr[8];

    const int tid = threadIdx.x;
    const int gid = blockIdx.x;
    const int b = (gid * 8) >> 11;
    const int qbase = (gid * 8) & (S_LEN - 1);
    const int qmax = qbase + 7;

    for (int i = tid; i < 8 * IDX_D; i += 256) {
        int r = i >> 8, c = i & 255;
        iqs[i] = iq[(size_t)(b * S_LEN + qbase + r) * IDX_D + c];
    }
    __syncthreads();

    for (int k0 = 0; k0 < S_LEN; k0 += 1024) {
        const int kb = k0 + tid;
        if (k0 <= qmax) {
            const float4* ikr[4];
#pragma unroll
            for (int j = 0; j < 4; j++) {
                int kj = kb + j * 256;
                int kc = kj <= qmax ? kj : qmax;
                ikr[j] = (const float4*)(ik + (size_t)(b * S_LEN + kc) * IDX_D);
            }
            float acc[4][8];
#pragma unroll
            for (int j = 0; j < 4; j++)
#pragma unroll
                for (int r = 0; r < 8; r++) acc[j][r] = 0.f;

#pragma unroll 2
            for (int i = 0; i < 64; i++) {
                float4 c0 = ikr[0][i];
                float4 c1 = ikr[1][i];
                float4 c2 = ikr[2][i];
                float4 c3 = ikr[3][i];
#pragma unroll
                for (int r = 0; r < 8; r++) {
                    float4 a = ((const float4*)(iqs + r * 256))[i];
                    acc[0][r] += a.x * c0.x + a.y * c0.y + a.z * c0.z + a.w * c0.w;
                    acc[1][r] += a.x * c1.x + a.y * c1.y + a.z * c1.z + a.w * c1.w;
                    acc[2][r] += a.x * c2.x + a.y * c2.y + a.z * c2.z + a.w * c2.w;
                    acc[3][r] += a.x * c3.x + a.y * c3.y + a.z * c3.z + a.w * c3.w;
                }
            }
#pragma unroll
            for (int j = 0; j < 4; j++) {
                int kj = kb + j * 256;
#pragma unroll
                for (int r = 0; r < 8; r++) {
                    unsigned key = 0u;
                    if (kj <= qbase + r) {
                        unsigned u = __float_as_uint(acc[j][r]);
                        key = (u & 0x80000000u) ? ~u : (u | 0x80000000u);
                    }
                    keys[r * S_LEN + kj] = key;
                }
            }
        } else {
#pragma unroll
            for (int j = 0; j < 4; j++) {
                int kj = kb + j * 256;
#pragma unroll
                for (int r = 0; r < 8; r++) keys[r * S_LEN + kj] = 0u;
            }
        }
    }

    int topk = topk_ptr ? topk_ptr[0] : 512;
    if (topk > S_LEN) topk = S_LEN;

    const int row  = tid >> 5;
    const int lane = tid & 31;
    const bool active = (qbase + row + 1 > topk);
    if (lane == 0) { s_prefix[row] = 0u; s_kr[row] = topk; }
    __syncthreads();

    for (int pass = 0; pass < 4; pass++) {
        const int shift = 24 - pass * 8;
        for (int i = tid; i < 8 * 256; i += 256) hist[i] = 0u;
        __syncthreads();
        if (active) {
            const unsigned pref = s_prefix[row];
            const unsigned* kr = keys + row * S_LEN;
            for (int k = lane; k < S_LEN; k += 32) {
                unsigned key = kr[k];
                bool match = (pass == 0) || ((key >> (shift + 8)) == (pref >> (shift + 8)));
                if (match) atomicAdd(&hist[row * 256 + ((key >> shift) & 255u)], 1u);
            }
        }
        __syncthreads();
        if (active && lane == 0) {
            int kk = s_kr[row];
            unsigned p = s_prefix[row];
            const unsigned* hr = hist + row * 256;
            for (int d = 255; d >= 0; d--) {
                int c = (int)hr[d];
                if (kk <= c) { s_prefix[row] = p | ((unsigned)d << shift); break; }
                kk -= c;
            }
            s_kr[row] = kk;
        }
        __syncthreads();
    }
    if (lane == 0) s_thr[row] = active ? s_prefix[row] : 0u;
    __syncthreads();

    for (int w = tid; w < 8 * 64; w += 256) {
        int r = w >> 6, wi = w & 63;
        int q = qbase + r;
        unsigned thr = s_thr[r];
        const unsigned* kr = keys + r * S_LEN;
        unsigned word = 0u;
        int kb2 = wi * 32;
#pragma unroll
        for (int bit = 0; bit < 32; bit++) {
            int k = kb2 + bit;
            unsigned key = kr[k];
            if (k <= q && key >= thr && key != 0u) word |= (1u << bit);
        }
        mask[(size_t)(b * S_LEN + q) * 64 + wi] = word;
    }
}

// ---------------- FA2-style tensor-core masked flash (validated) ----------------
#define KSTR   72
#define KSTRB  144
#define KTILE  (64 * KSTR)
#define FSMEM3 (8 * KTILE * 2)    // 73728 bytes

__global__ __launch_bounds__(256) void flash_mma3(
    const bf16* __restrict__ qh, const bf16* __restrict__ ql,
    const bf16* __restrict__ kh, const bf16* __restrict__ kl,
    const bf16* __restrict__ vth, const bf16* __restrict__ vtl,
    const unsigned* __restrict__ mask, bf16* __restrict__ attn3)
{
    extern __shared__ __align__(16) bf16 sm[];
    const int tid  = threadIdx.x;
    const int warp = tid >> 5, lane = tid & 31;
    const int qt = gridDim.x - 1 - blockIdx.x;
    const int hd = blockIdx.y, b = blockIdx.z;

    const uint32_t sbase = (uint32_t)__cvta_generic_to_shared(sm);

    const size_t bh = (size_t)b * N_HEADS + hd;
    const bf16* qhg  = qh  + (bh * S_LEN + (size_t)qt * 128) * 64;
    const bf16* qlg  = ql  + (bh * S_LEN + (size_t)qt * 128) * 64;
    const bf16* khg  = kh  + bh * S_LEN * 64;
    const bf16* klg  = kl  + bh * S_LEN * 64;
    const bf16* vthg = vth + bh * 64 * (size_t)S_LEN;
    const bf16* vtlg = vtl + bh * 64 * (size_t)S_LEN;

    const uint32_t QHS = sbase + (4 * KTILE) * 2;
    const uint32_t QLS = sbase + (6 * KTILE) * 2;
    for (int c = tid; c < 2048; c += 256) {
        if (c < 1024) {
            int row = c >> 3, ch = c & 7;
            CP16(QHS + row * KSTRB + ch * 16, qhg + (size_t)row * 64 + ch * 8);
        } else {
            int cc = c - 1024;
            int row = cc >> 3, ch = cc & 7;
            CP16(QLS + row * KSTRB + ch * 16, qlg + (size_t)row * 64 + ch * 8);
        }
    }
    CPCOMMIT();

    for (int c = tid; c < 2048; c += 256) {
        int q4 = c >> 9, idx = c & 511;
        int row = idx >> 3, ch = idx & 7;
        uint32_t dst = sbase + (uint32_t)q4 * (KTILE * 2) + row * KSTRB + ch * 16;
        const bf16* src;
        if      (q4 == 0) src = khg  + (size_t)row * 64 + ch * 8;
        else if (q4 == 1) src = klg  + (size_t)row * 64 + ch * 8;
        else if (q4 == 2) src = vthg + (size_t)row * S_LEN + ch * 8;
        else              src = vtlg + (size_t)row * S_LEN + ch * 8;
        CP16(dst, src);
    }
    CPCOMMIT();
    CPWAIT0();
    __syncthreads();

    uint32_t aQh[4][4], aQl[4][4];
    const uint32_t qro = (uint32_t)((warp * 16 + (lane & 15)) * KSTRB + ((lane >> 4) << 3) * 2);
#pragma unroll
    for (int ks = 0; ks < 4; ks++) {
        ldsm_x4(aQh[ks], QHS + qro + ks * 32);
        ldsm_x4(aQl[ks], QLS + qro + ks * 32);
    }
    __syncthreads();

    float O[8][4];
#pragma unroll
    for (int i = 0; i < 8; i++)
#pragma unroll
        for (int j = 0; j < 4; j++) O[i][j] = 0.f;
    float m0 = -1e30f, m1 = -1e30f, l0 = 0.f, l1 = 0.f;

    const int r0 = warp * 16 + (lane >> 2);
    const int q0 = qt * 128 + r0, q1 = q0 + 8;
    const unsigned* mrow0 = mask + ((size_t)b * S_LEN + q0) * 64;
    const unsigned* mrow1 = mask + ((size_t)b * S_LEN + q1) * 64;

    const int browo = (lane & 7) + ((lane >> 4) << 3);
    const uint32_t bcol = (uint32_t)((((lane >> 3) & 1) << 3) * 2);

    const int ktmax = 2 * qt + 1;

    for (int kt = 0; kt <= ktmax; kt++) {
        const int buf = kt & 1;
        if (kt < ktmax) {
            const uint32_t dbase = sbase + (uint32_t)(buf ^ 1) * (4 * KTILE * 2);
            const size_t kro = (size_t)(kt + 1) * 64;
            for (int c = tid; c < 2048; c += 256) {
                int q4 = c >> 9, idx = c & 511;
                int row = idx >> 3, ch = idx & 7;
                uint32_t dst = dbase + (uint32_t)q4 * (KTILE * 2) + row * KSTRB + ch * 16;
                const bf16* src;
                if      (q4 == 0) src = khg  + (kro + row) * 64 + ch * 8;
                else if (q4 == 1) src = klg  + (kro + row) * 64 + ch * 8;
                else if (q4 == 2) src = vthg + (size_t)row * S_LEN + kro + ch * 8;
                else              src = vtlg + (size_t)row * S_LEN + kro + ch * 8;
                CP16(dst, src);
            }
            CPCOMMIT();
            CPWAIT1();
        } else {
            CPWAIT0();
        }
        __syncthreads();

        const uint32_t tb  = sbase + (uint32_t)buf * (4 * KTILE * 2);
        const uint32_t sKh = tb;
        const uint32_t sKl = tb + KTILE * 2;
        const uint32_t sVh = tb + 2 * KTILE * 2;
        const uint32_t sVl = tb + 3 * KTILE * 2;

        float S_[8][4];
#pragma unroll
        for (int i = 0; i < 8; i++)
#pragma unroll
            for (int j = 0; j < 4; j++) S_[i][j] = 0.f;

#pragma unroll
        for (int ks = 0; ks < 4; ks++) {
#pragma unroll
            for (int nt2 = 0; nt2 < 4; nt2++) {
                const uint32_t ro = (uint32_t)((nt2 * 16 + browo) * KSTRB) + bcol + ks * 32;
                uint32_t bb[4];
                ldsm_x4(bb, sKh + ro);
                mma16816(S_[nt2 * 2],     aQh[ks], bb);
                mma16816(S_[nt2 * 2 + 1], aQh[ks], bb + 2);
                mma16816(S_[nt2 * 2],     aQl[ks], bb);
                mma16816(S_[nt2 * 2 + 1], aQl[ks], bb + 2);
                ldsm_x4(bb, sKl + ro);
                mma16816(S_[nt2 * 2],     aQh[ks], bb);
                mma16816(S_[nt2 * 2 + 1], aQh[ks], bb + 2);
            }
        }

        const unsigned mw00 = mrow0[kt * 2], mw01 = mrow0[kt * 2 + 1];
        const unsigned mw10 = mrow1[kt * 2], mw11 = mrow1[kt * 2 + 1];
        float mx0 = -1e30f, mx1 = -1e30f;
#pragma unroll
        for (int nf = 0; nf < 8; nf++) {
            int c = nf * 8 + 2 * (lane & 3);
#pragma unroll
            for (int e = 0; e < 2; e++) {
                int cc = c + e;
                unsigned w0 = (cc < 32 ? mw00 : mw01) >> (cc & 31);
                unsigned w1 = (cc < 32 ? mw10 : mw11) >> (cc & 31);
                float v0 = (w0 & 1u) ? S_[nf][e] * 0.125f     : -1e30f;
                float v1 = (w1 & 1u) ? S_[nf][e + 2] * 0.125f : -1e30f;
                S_[nf][e] = v0; S_[nf][e + 2] = v1;
                mx0 = fmaxf(mx0, v0); mx1 = fmaxf(mx1, v1);
            }
        }
        mx0 = fmaxf(mx0, __shfl_xor_sync(0xffffffffu, mx0, 1));
        mx0 = fmaxf(mx0, __shfl_xor_sync(0xffffffffu, mx0, 2));
        mx1 = fmaxf(mx1, __shfl_xor_sync(0xffffffffu, mx1, 1));
        mx1 = fmaxf(mx1, __shfl_xor_sync(0xffffffffu, mx1, 2));
        float mn0 = fmaxf(m0, mx0), mn1 = fmaxf(m1, mx1);
        float c0 = __expf(m0 - mn0), c1 = __expf(m1 - mn1);
        float ls0 = 0.f, ls1 = 0.f;
#pragma unroll
        for (int nf = 0; nf < 8; nf++) {
#pragma unroll
            for (int e = 0; e < 2; e++) {
                float p0 = (S_[nf][e]     > -1e29f) ? __expf(S_[nf][e]     - mn0) : 0.f;
                float p1 = (S_[nf][e + 2] > -1e29f) ? __expf(S_[nf][e + 2] - mn1) : 0.f;
                S_[nf][e] = p0; S_[nf][e + 2] = p1;
                ls0 += p0; ls1 += p1;
            }
        }
        ls0 += __shfl_xor_sync(0xffffffffu, ls0, 1);
        ls0 += __shfl_xor_sync(0xffffffffu, ls0, 2);
        ls1 += __shfl_xor_sync(0xffffffffu, ls1, 1);
        ls1 += __shfl_xor_sync(0xffffffffu, ls1, 2);
        l0 = l0 * c0 + ls0; l1 = l1 * c1 + ls1;
        m0 = mn0; m1 = mn1;
#pragma unroll
        for (int nf = 0; nf < 8; nf++) {
            O[nf][0] *= c0; O[nf][1] *= c0;
            O[nf][2] *= c1; O[nf][3] *= c1;
        }

        uint32_t aPh[4][4], aPl[4][4];
#pragma unroll
        for (int ks = 0; ks < 4; ks++) {
#pragma unroll
            for (int half = 0; half < 2; half++) {
                const float* Sf = S_[2 * ks + half];
                bf16 h0 = __float2bfloat16(Sf[0]);
                bf16 l0b = __float2bfloat16(Sf[0] - __bfloat162float(h0));
                bf16 h1 = __float2bfloat16(Sf[1]);
                bf16 l1b = __float2bfloat16(Sf[1] - __bfloat162float(h1));
                bf16 h2 = __float2bfloat16(Sf[2]);
                bf16 l2b = __float2bfloat16(Sf[2] - __bfloat162float(h2));
                bf16 h3 = __float2bfloat16(Sf[3]);
                bf16 l3b = __float2bfloat16(Sf[3] - __bfloat162float(h3));
                aPh[ks][half * 2]     = pack_bf2(h0, h1);
                aPh[ks][half * 2 + 1] = pack_bf2(h2, h3);
                aPl[ks][half * 2]     = pack_bf2(l0b, l1b);
                aPl[ks][half * 2 + 1] = pack_bf2(l2b, l3b);
            }
        }

#pragma unroll
        for (int ks = 0; ks < 4; ks++) {
#pragma unroll
            for (int nt2 = 0; nt2 < 4; nt2++) {
                const uint32_t ro = (uint32_t)((nt2 * 16 + browo) * KSTRB) + bcol + ks * 32;
                uint32_t bb[4];
                ldsm_x4(bb, sVh + ro);
                mma16816(O[nt2 * 2],     aPh[ks], bb);
                mma16816(O[nt2 * 2 + 1], aPh[ks], bb + 2);
                mma16816(O[nt2 * 2],     aPl[ks], bb);
                mma16816(O[nt2 * 2 + 1], aPl[ks], bb + 2);
                ldsm_x4(bb, sVl + ro);
                mma16816(O[nt2 * 2],     aPh[ks], bb);
                mma16816(O[nt2 * 2 + 1], aPh[ks], bb + 2);
            }
        }
        __syncthreads();
    }

    float inv0 = 1.0f / l0, inv1 = 1.0f / l1;
    bf16* o3r0 = attn3 + ((size_t)b * S_LEN + q0) * 3072;
    bf16* o3r1 = attn3 + ((size_t)b * S_LEN + q1) * 3072;
#pragma unroll
    for (int nf = 0; nf < 8; nf++) {
        int c = nf * 8 + 2 * (lane & 3);
        {
            float v0 = O[nf][0] * inv0, v1 = O[nf][1] * inv0;
            bf16 h0 = __float2bfloat16(v0);
            bf16 l0b = __float2bfloat16(v0 - __bfloat162float(h0));
            bf16 h1 = __float2bfloat16(v1);
            bf16 l1b = __float2bfloat16(v1 - __bfloat162float(h1));
            uint32_t* p = (uint32_t*)(o3r0 + 3 * (size_t)(hd * 64 + c));
            p[0] = pack_bf2(h0, l0b);
            p[1] = pack_bf2(h0, h1);
            p[2] = pack_bf2(l1b, h1);
        }
        {
            float v0 = O[nf][2] * inv1, v1 = O[nf][3] * inv1;
            bf16 h0 = __float2bfloat16(v0);
            bf16 l0b = __float2bfloat16(v0 - __bfloat162float(h0));
            bf16 h1 = __float2bfloat16(v1);
            bf16 l1b = __float2bfloat16(v1 - __bfloat162float(h1));
            uint32_t* p = (uint32_t*)(o3r1 + 3 * (size_t)(hd * 64 + c));
            p[0] = pack_bf2(h0, l0b);
            p[1] = pack_bf2(h0, h1);
            p[2] = pack_bf2(l1b, h1);
        }
    }
}

// ---------------- launcher with fork/join stream overlap -------------------------
extern "C" void kernel_launch(void* const* d_in, const int* in_sizes, int n_in,
                              void* d_out, int out_size)
{
    static cudaStream_t s_sel = nullptr;
    static cudaEvent_t  ev_fork = nullptr, ev_join = nullptr, ev_wo = nullptr;
    if (!s_sel) {
        cudaStreamCreateWithFlags(&s_sel, cudaStreamNonBlocking);
        cudaEventCreateWithFlags(&ev_fork, cudaEventDisableTiming);
        cudaEventCreateWithFlags(&ev_join, cudaEventDisableTiming);
        cudaEventCreateWithFlags(&ev_wo, cudaEventDisableTiming);
    }

    const float* x    = nullptr;
    const float* Wqkv = nullptr;
    const float* Wo   = nullptr;
    const float* Wiq  = nullptr;
    const float* Wik  = nullptr;
    const int*   topk = nullptr;
    for (int i = 0; i < n_in; i++) {
        int sz = in_sizes[i];
        if      (sz == D_MODEL * 3 * D_MODEL)       Wqkv = (const float*)d_in[i];
        else if (sz == D_MODEL * D_MODEL)           Wo   = (const float*)d_in[i];
        else if (sz == D_MODEL * IDX_D) { if (!Wiq) Wiq  = (const float*)d_in[i];
                                          else      Wik  = (const float*)d_in[i]; }
        else if (sz <= 4)                           topk = (const int*)d_in[i];
        else                                        x    = (const float*)d_in[i];
    }

    const int BS = out_size / D_MODEL;
    const int Bn = BS / S_LEN;

    float *iq, *ik; unsigned* mask;
    bf16 *x3, *attn3, *wqkv3, *wo3, *qh, *ql, *kh, *kl, *vth, *vtl;
    cudaGetSymbolAddress((void**)&iq,    g_iq);
    cudaGetSymbolAddress((void**)&ik,    g_ik);
    cudaGetSymbolAddress((void**)&mask,  g_mask);
    cudaGetSymbolAddress((void**)&x3,    g_x3);
    cudaGetSymbolAddress((void**)&attn3, g_attn3);
    cudaGetSymbolAddress((void**)&wqkv3, g_wqkv3);
    cudaGetSymbolAddress((void**)&wo3,   g_wo3);
    cudaGetSymbolAddress((void**)&qh,    g_qh);
    cudaGetSymbolAddress((void**)&ql,    g_ql);
    cudaGetSymbolAddress((void**)&kh,    g_kh);
    cudaGetSymbolAddress((void**)&kl,    g_kl);
    cudaGetSymbolAddress((void**)&vth,   g_vth);
    cudaGetSymbolAddress((void**)&vtl,   g_vtl);

    const int K3 = 3 * D_MODEL;
    const int TOPK_SMEM = (8 * 256 + 8 * 2048 + 8 * 256) * 4;

    cudaFuncSetAttribute(mma_gemm, cudaFuncAttributeMaxDynamicSharedMemorySize, GEMM_SMEM);
    cudaFuncSetAttribute(mma_gemm_qkv, cudaFuncAttributeMaxDynamicSharedMemorySize, GEMM_SMEM);
    cudaFuncSetAttribute(topk8_kernel, cudaFuncAttributeMaxDynamicSharedMemorySize, TOPK_SMEM);
    cudaFuncSetAttribute(flash_mma3, cudaFuncAttributeMaxDynamicSharedMemorySize, FSMEM3);

    // ---- fork: pure selection chain on s_sel (starts immediately) ----
    cudaEventRecord(ev_fork, 0);
    cudaStreamWaitEvent(s_sel, ev_fork, 0);
    sgemm_nn2<<<dim3(IDX_D / 64, BS / 64, 2), 256, 0, s_sel>>>(
        x, Wiq, iq, Wik, ik, BS, IDX_D, D_MODEL);
    topk8_kernel<<<BS / 8, 256, TOPK_SMEM, s_sel>>>(iq, ik, topk, mask);
    cudaEventRecord(ev_join, s_sel);
    // Wo weight split: only needed by the final GEMM; runs concurrently with flash
    {
        dim3 blk(32, 8);
        split_bT<<<dim3(D_MODEL / 32, D_MODEL / 32), blk, 0, s_sel>>>(Wo, wo3, D_MODEL, D_MODEL);
    }
    cudaEventRecord(ev_wo, s_sel);

    // ---- smooth chain on the main (capture) stream ----
    split_a<<<(BS * D_MODEL + 255) / 256, 256>>>(x, x3, BS * D_MODEL);
    {
        dim3 blk(32, 8);
        split_bT<<<dim3(3 * D_MODEL / 32, D_MODEL / 32), blk>>>(Wqkv, wqkv3, D_MODEL, 3 * D_MODEL);
    }
    mma_gemm_qkv<<<dim3(3 * D_MODEL / BNg, BS / BMg), 256, GEMM_SMEM>>>(
        x3, wqkv3, qh, ql, kh, kl, vth, vtl, K3);

    // ---- join: flash needs the mask ----
    cudaStreamWaitEvent(0, ev_join, 0);
    flash_mma3<<<dim3(S_LEN / 128, N_HEADS, Bn), 256, FSMEM3>>>(
        qh, ql, kh, kl, vth, vtl, mask, attn3);

    // output projection (needs wo3, ready well before flash completes)
    cudaStreamWaitEvent(0, ev_wo, 0);
    mma_gemm<<<dim3(D_MODEL / BNg, BS / BMg), 256, GEMM_SMEM>>>(
        attn3, wo3, (float*)d_out, BS, D_MODEL, K3);
}